// round 1
// baseline (speedup 1.0000x reference)
#include <cuda_runtime.h>
#include <cuda_bf16.h>
#include <math.h>

// Problem dims (fixed by the dataset)
#define T_DIM 800
#define B_DIM 16
#define D_DIM 256
#define V_DIM 4001
#define U_DIM 100
#define S_DIM 201            // 2*U+1
#define M_DIM (T_DIM * B_DIM)  // 12800
#define NEGV  (-1e30f)

// per-batch log-likelihood scratch (no allocation allowed)
__device__ float g_ll[B_DIM];

// ---------------------------------------------------------------------------
// Kernel 1: fp32 tiled SGEMM  C[M, V] = A[M, D] * W[D, V]   (no bias here)
// BM=BN=64, BK=16, 256 threads, 4x4 per-thread microtile
// ---------------------------------------------------------------------------
#define BM 64
#define BN 64
#define BK 16

__global__ __launch_bounds__(256) void sgemm_kernel(
    const float* __restrict__ A,   // [M, D]
    const float* __restrict__ Bw,  // [D, V]
    float* __restrict__ C)         // [M, V]
{
    __shared__ float As[BK][BM];
    __shared__ float Bs[BK][BN];

    int tid = threadIdx.x;
    int tx = tid & 15;        // 0..15  -> 4 cols each
    int ty = tid >> 4;        // 0..15  -> 4 rows each
    int bm = blockIdx.y * BM;
    int bn = blockIdx.x * BN;

    float acc[4][4];
#pragma unroll
    for (int i = 0; i < 4; i++)
#pragma unroll
        for (int j = 0; j < 4; j++) acc[i][j] = 0.f;

    // A loaded as float4 (D=256 -> 64 float4 per row, base aligned)
    const float4* A4 = reinterpret_cast<const float4*>(A);
    int am = tid >> 2;        // 0..63 row within tile
    int ak = tid & 3;         // 0..3  float4 within BK

    int bn_l = tid & 63;      // 0..63 col within tile
    int bk_l = tid >> 6;      // 0..3

#pragma unroll 1
    for (int k0 = 0; k0 < D_DIM; k0 += BK) {
        float4 va = A4[(size_t)(bm + am) * (D_DIM / 4) + (k0 >> 2) + ak];
        As[ak * 4 + 0][am] = va.x;
        As[ak * 4 + 1][am] = va.y;
        As[ak * 4 + 2][am] = va.z;
        As[ak * 4 + 3][am] = va.w;

        int col = bn + bn_l;
#pragma unroll
        for (int i = 0; i < 4; i++) {
            int k = bk_l + i * 4;
            Bs[k][bn_l] = (col < V_DIM) ? Bw[(size_t)(k0 + k) * V_DIM + col] : 0.f;
        }
        __syncthreads();

#pragma unroll
        for (int k = 0; k < BK; k++) {
            float a[4], bb[4];
#pragma unroll
            for (int i = 0; i < 4; i++) a[i] = As[k][ty * 4 + i];
#pragma unroll
            for (int j = 0; j < 4; j++) bb[j] = Bs[k][tx * 4 + j];
#pragma unroll
            for (int i = 0; i < 4; i++)
#pragma unroll
                for (int j = 0; j < 4; j++) acc[i][j] = fmaf(a[i], bb[j], acc[i][j]);
        }
        __syncthreads();
    }

#pragma unroll
    for (int i = 0; i < 4; i++) {
        int row = bm + ty * 4 + i;
#pragma unroll
        for (int j = 0; j < 4; j++) {
            int col = bn + tx * 4 + j;
            if (col < V_DIM) C[(size_t)row * V_DIM + col] = acc[i][j];
        }
    }
}

// ---------------------------------------------------------------------------
// Kernel 2: in-place log_softmax per row, bias folded in.
// One block per row of 4001, row staged in shared memory.
// ---------------------------------------------------------------------------
__global__ __launch_bounds__(256) void logsoftmax_kernel(
    float* __restrict__ logits,          // [M, V] in/out
    const float* __restrict__ bias)      // [V]
{
    __shared__ float row[V_DIM];
    __shared__ float red[256];

    int r = blockIdx.x;
    int tid = threadIdx.x;
    float* p = logits + (size_t)r * V_DIM;

    for (int v = tid; v < V_DIM; v += 256) row[v] = p[v] + bias[v];
    __syncthreads();

    // block max
    float m = -INFINITY;
    for (int v = tid; v < V_DIM; v += 256) m = fmaxf(m, row[v]);
    red[tid] = m;
    __syncthreads();
    for (int s = 128; s > 0; s >>= 1) {
        if (tid < s) red[tid] = fmaxf(red[tid], red[tid + s]);
        __syncthreads();
    }
    float mx = red[0];
    __syncthreads();

    // block sum of exp
    float sum = 0.f;
    for (int v = tid; v < V_DIM; v += 256) sum += expf(row[v] - mx);
    red[tid] = sum;
    __syncthreads();
    for (int s = 128; s > 0; s >>= 1) {
        if (tid < s) red[tid] += red[tid + s];
        __syncthreads();
    }
    float lse = mx + logf(red[0]);

    for (int v = tid; v < V_DIM; v += 256) p[v] = row[v] - lse;
}

// ---------------------------------------------------------------------------
// Kernel 3: CTC forward recursion. One block per batch element.
// alpha double-buffered in SMEM, one __syncthreads per time step.
// ---------------------------------------------------------------------------
__device__ __forceinline__ float lae(float a, float b) {
    // jnp.logaddexp: max + log1p(exp(min - max)); handles -1e30 sentinels fine
    float m = fmaxf(a, b);
    float d = fminf(a, b) - m;
    return m + log1pf(__expf(d));
}

__global__ __launch_bounds__(256) void ctc_kernel(
    const float* __restrict__ logp,  // [T, B, V] log-probs
    const int*   __restrict__ y)     // [U, B] labels (pad = 1)
{
    int b = blockIdx.x;
    int tid = threadIdx.x;

    __shared__ int   ext[S_DIM];
    __shared__ float alpha[2][S_DIM];
    __shared__ int   len_s;

    if (tid == 0) len_s = 0;
    __syncthreads();
    if (tid < U_DIM) {
        if (y[tid * B_DIM + b] != 1) atomicAdd(&len_s, 1);
    }
    if (tid < S_DIM) {
        int e = (tid & 1) ? y[((tid - 1) >> 1) * B_DIM + b] : 0;
        ext[tid] = e;
    }
    __syncthreads();

    int  myext   = (tid < S_DIM) ? ext[tid] : 0;
    bool myallow = false;
    if (tid < S_DIM && tid >= 2)
        myallow = (myext != 0) && (myext != ext[tid - 2]);

    if (tid < S_DIM) {
        float e0 = logp[(size_t)b * V_DIM + myext];  // t = 0 row
        alpha[0][tid] = (tid < 2) ? e0 : NEGV;
    }
    __syncthreads();

    int p = 0;
    for (int t = 1; t < T_DIM; t++) {
        float r = NEGV;
        if (tid < S_DIM) {
            float e  = logp[((size_t)t * B_DIM + b) * V_DIM + myext];
            float a0 = alpha[p][tid];
            float a1 = (tid >= 1) ? alpha[p][tid - 1] : NEGV;
            float a2 = myallow ? alpha[p][tid - 2] : NEGV;
            r = lae(lae(a0, a1), a2) + e;
            alpha[p ^ 1][tid] = r;
        }
        __syncthreads();
        p ^= 1;
    }

    if (tid == 0) {
        int end = 2 * len_s;  // len >= 50, so end-1 >= 99 is valid
        g_ll[b] = lae(alpha[p][end], alpha[p][end - 1]);
    }
}

// ---------------------------------------------------------------------------
// Kernel 4: finalize loss = -sum_b ll_b
// ---------------------------------------------------------------------------
__global__ void finalize_kernel(float* __restrict__ out) {
    if (threadIdx.x == 0) {
        float s = 0.f;
        for (int b = 0; b < B_DIM; b++) s += g_ll[b];
        out[0] = -s;
    }
}

// ---------------------------------------------------------------------------
// Launch: out = [loss(1), logps(T*B*V)]
// ---------------------------------------------------------------------------
extern "C" void kernel_launch(void* const* d_in, const int* in_sizes, int n_in,
                              void* d_out, int out_size)
{
    const float* ctx  = (const float*)d_in[0];   // [T, B, D]
    const int*   y    = (const int*)  d_in[1];   // [U, B]
    const float* W    = (const float*)d_in[2];   // [D, V]
    const float* bias = (const float*)d_in[3];   // [V]

    float* out   = (float*)d_out;
    float* logps = out + 1;                      // [T, B, V] region

    dim3 gemm_grid((V_DIM + BN - 1) / BN, M_DIM / BM);  // (63, 200)
    sgemm_kernel<<<gemm_grid, 256>>>(ctx, W, logps);
    logsoftmax_kernel<<<M_DIM, 256>>>(logps, bias);
    ctc_kernel<<<B_DIM, 256>>>(logps, y);
    finalize_kernel<<<1, 32>>>(out);
}

// round 3
// speedup vs baseline: 1.5982x; 1.5982x over previous
#include <cuda_runtime.h>
#include <cuda_bf16.h>
#include <math.h>
#include <stdint.h>

// Problem dims (fixed by the dataset)
#define T_DIM 800
#define B_DIM 16
#define D_DIM 256
#define V_DIM 4001
#define U_DIM 100
#define S_DIM 201              // 2*U+1
#define M_DIM (T_DIM * B_DIM) // 12800
#define NEGV  (-1e30f)

__device__ float g_ll[B_DIM];

__device__ __forceinline__ uint32_t smem_u32(const void* p) {
    uint32_t a;
    asm("{ .reg .u64 t; cvta.to.shared.u64 t, %1; cvt.u32.u64 %0, t; }" : "=r"(a) : "l"(p));
    return a;
}

// ---------------------------------------------------------------------------
// Kernel 1: bf16 HMMA GEMM  C[M, V] = A[M, D] * W[D, V]  (raw logits)
// CTA tile 128x128, full K=256 in SMEM. 8 warps, warp tile 64x32.
// mma.sync.aligned.m16n8k16.row.col.f32.bf16.bf16.f32 (family-portable).
// ---------------------------------------------------------------------------
#define BM 128
#define BN 128
#define APITCH 264                       // 256 + 8 bf16 pad -> 528B row stride
#define SM_A_BYTES (BM * APITCH * 2)     // 67584
#define SMEM_TOTAL (2 * SM_A_BYTES)      // 135168 (A then B)
#define STG_PITCH 132                    // fp32 stage pitch

__global__ __launch_bounds__(256) void gemm_mma_kernel(
    const float* __restrict__ A,   // [M, D]
    const float* __restrict__ W,   // [D, V]
    float* __restrict__ C)         // [M, V]
{
    extern __shared__ char smem[];
    __nv_bfloat16* As = reinterpret_cast<__nv_bfloat16*>(smem);
    __nv_bfloat16* Bs = reinterpret_cast<__nv_bfloat16*>(smem + SM_A_BYTES);

    const int tid  = threadIdx.x;
    const int wid  = tid >> 5;
    const int lane = tid & 31;
    const int bm = blockIdx.y * BM;
    const int bn = blockIdx.x * BN;

    // ---- fill A tile: 128 x 256 fp32 -> bf16 (coalesced float2 loads) ----
    const float2* A2 = reinterpret_cast<const float2*>(A + (size_t)bm * D_DIM);
#pragma unroll
    for (int i = 0; i < 64; i++) {
        int idx = i * 256 + tid;
        int row = idx >> 7;          // 0..127
        int kp  = idx & 127;         // float2 index (k = 2*kp)
        float2 v = A2[row * 128 + kp];
        __nv_bfloat162 h = __floats2bfloat162_rn(v.x, v.y);
        *reinterpret_cast<uint32_t*>(&As[row * APITCH + kp * 2]) =
            *reinterpret_cast<uint32_t*>(&h);
    }
    // ---- fill B tile: W[k][bn+n] -> Bs[n][k] (transpose, zero-pad tail) ----
#pragma unroll 8
    for (int i = 0; i < 128; i++) {
        int idx = i * 256 + tid;
        int n = idx & 127;
        int k = idx >> 7;            // 0..255
        int col = bn + n;
        float v = (col < V_DIM) ? __ldg(&W[(size_t)k * V_DIM + col]) : 0.f;
        Bs[n * APITCH + k] = __float2bfloat16(v);
    }
    __syncthreads();

    // ---- mainloop: 16 K-steps of m16n8k16 ----
    const int wm = wid & 1;          // 2 warps along M
    const int wn = wid >> 1;         // 4 warps along N
    const int m0 = wm * 64;
    const int n0 = wn * 32;

    float acc[4][4][4];
#pragma unroll
    for (int mt = 0; mt < 4; mt++)
#pragma unroll
        for (int nt = 0; nt < 4; nt++)
#pragma unroll
            for (int r = 0; r < 4; r++) acc[mt][nt][r] = 0.f;

    // per-lane ldmatrix source rows (constant across K-steps)
    const int a_row = m0 + (lane & 15);          // + mt*16
    const int a_koff = (lane >> 4) * 8;
    const int b_row = n0 + (lane & 7);           // + nt*8
    const int b_koff = ((lane >> 3) & 1) * 8;

    uint32_t as_base = smem_u32(As);
    uint32_t bs_base = smem_u32(Bs);

    for (int ks = 0; ks < 16; ks++) {
        int k0 = ks * 16;
        uint32_t af[4][4], bf[4][2];
#pragma unroll
        for (int mt = 0; mt < 4; mt++) {
            uint32_t addr = as_base + ((a_row + mt * 16) * APITCH + k0 + a_koff) * 2;
            asm volatile("ldmatrix.sync.aligned.m8n8.x4.shared.b16 {%0,%1,%2,%3}, [%4];"
                         : "=r"(af[mt][0]), "=r"(af[mt][1]), "=r"(af[mt][2]), "=r"(af[mt][3])
                         : "r"(addr));
        }
#pragma unroll
        for (int nt = 0; nt < 4; nt++) {
            uint32_t addr = bs_base + ((b_row + nt * 8) * APITCH + k0 + b_koff) * 2;
            asm volatile("ldmatrix.sync.aligned.m8n8.x2.shared.b16 {%0,%1}, [%2];"
                         : "=r"(bf[nt][0]), "=r"(bf[nt][1])
                         : "r"(addr));
        }
#pragma unroll
        for (int mt = 0; mt < 4; mt++)
#pragma unroll
            for (int nt = 0; nt < 4; nt++) {
                asm volatile(
                    "mma.sync.aligned.m16n8k16.row.col.f32.bf16.bf16.f32 "
                    "{%0,%1,%2,%3}, {%4,%5,%6,%7}, {%8,%9}, {%0,%1,%2,%3};"
                    : "+f"(acc[mt][nt][0]), "+f"(acc[mt][nt][1]),
                      "+f"(acc[mt][nt][2]), "+f"(acc[mt][nt][3])
                    : "r"(af[mt][0]), "r"(af[mt][1]), "r"(af[mt][2]), "r"(af[mt][3]),
                      "r"(bf[nt][0]), "r"(bf[nt][1]));
            }
    }
    __syncthreads();   // mainloop reads of As/Bs done CTA-wide before reuse

    // ---- stage C through padded SMEM, then coalesced global stores ----
    float* stage = reinterpret_cast<float*>(smem);
    {
        const int crow = lane >> 2;
        const int ccol = (lane & 3) * 2;
#pragma unroll
        for (int mt = 0; mt < 4; mt++)
#pragma unroll
            for (int nt = 0; nt < 4; nt++) {
                int r0 = m0 + mt * 16 + crow;
                int c0 = n0 + nt * 8 + ccol;
                float2 lo = make_float2(acc[mt][nt][0], acc[mt][nt][1]);
                float2 hi = make_float2(acc[mt][nt][2], acc[mt][nt][3]);
                *reinterpret_cast<float2*>(&stage[r0 * STG_PITCH + c0]) = lo;
                *reinterpret_cast<float2*>(&stage[(r0 + 8) * STG_PITCH + c0]) = hi;
            }
    }
    __syncthreads();
#pragma unroll
    for (int i = 0; i < 64; i++) {
        int idx = i * 256 + tid;
        int col = idx & 127;
        int row = idx >> 7;
        int gc = bn + col;
        if (gc < V_DIM)
            C[(size_t)(bm + row) * V_DIM + gc] = stage[row * STG_PITCH + col];
    }
}

// ---------------------------------------------------------------------------
// Kernel 2: in-place log_softmax per row, bias folded in.
// ---------------------------------------------------------------------------
__global__ __launch_bounds__(256) void logsoftmax_kernel(
    float* __restrict__ logits,          // [M, V] in/out
    const float* __restrict__ bias)      // [V]
{
    __shared__ float row[V_DIM];
    __shared__ float red[256];

    int r = blockIdx.x;
    int tid = threadIdx.x;
    float* p = logits + (size_t)r * V_DIM;

    for (int v = tid; v < V_DIM; v += 256) row[v] = p[v] + bias[v];
    __syncthreads();

    float m = -INFINITY;
    for (int v = tid; v < V_DIM; v += 256) m = fmaxf(m, row[v]);
    red[tid] = m;
    __syncthreads();
    for (int s = 128; s > 0; s >>= 1) {
        if (tid < s) red[tid] = fmaxf(red[tid], red[tid + s]);
        __syncthreads();
    }
    float mx = red[0];
    __syncthreads();

    float sum = 0.f;
    for (int v = tid; v < V_DIM; v += 256) sum += expf(row[v] - mx);
    red[tid] = sum;
    __syncthreads();
    for (int s = 128; s > 0; s >>= 1) {
        if (tid < s) red[tid] += red[tid + s];
        __syncthreads();
    }
    float lse = mx + logf(red[0]);

    for (int v = tid; v < V_DIM; v += 256) p[v] = row[v] - lse;
}

// ---------------------------------------------------------------------------
// Kernel 3: CTC forward recursion. One block per batch element.
// Emission prefetch (t+1) + fast logaddexp.
// ---------------------------------------------------------------------------
__device__ __forceinline__ float lae(float a, float b) {
    float m = fmaxf(a, b);
    float d = fminf(a, b) - m;            // d <= 0, exp(d) in (0, 1]
    return m + __logf(1.0f + __expf(d));  // no cancellation: arg >= 1
}

__global__ __launch_bounds__(256) void ctc_kernel(
    const float* __restrict__ logp,  // [T, B, V] log-probs
    const int*   __restrict__ y)     // [U, B] labels (pad = 1)
{
    int b = blockIdx.x;
    int tid = threadIdx.x;

    __shared__ int   ext[S_DIM];
    __shared__ float alpha[2][S_DIM];
    __shared__ int   len_s;

    if (tid == 0) len_s = 0;
    __syncthreads();
    if (tid < U_DIM) {
        if (y[tid * B_DIM + b] != 1) atomicAdd(&len_s, 1);
    }
    if (tid < S_DIM) {
        int e = (tid & 1) ? y[((tid - 1) >> 1) * B_DIM + b] : 0;
        ext[tid] = e;
    }
    __syncthreads();

    int  myext   = (tid < S_DIM) ? ext[tid] : 0;
    bool myallow = false;
    if (tid < S_DIM && tid >= 2)
        myallow = (myext != 0) && (myext != ext[tid - 2]);

    float e_next = 0.f;
    if (tid < S_DIM) {
        float e0 = logp[(size_t)b * V_DIM + myext];                 // t = 0
        alpha[0][tid] = (tid < 2) ? e0 : NEGV;
        e_next = logp[((size_t)1 * B_DIM + b) * V_DIM + myext];     // t = 1 prefetch
    }
    __syncthreads();

    int p = 0;
    for (int t = 1; t < T_DIM; t++) {
        if (tid < S_DIM) {
            float e = e_next;
            int tn = (t + 1 < T_DIM) ? (t + 1) : t;
            e_next = logp[((size_t)tn * B_DIM + b) * V_DIM + myext];  // prefetch t+1
            float a0 = alpha[p][tid];
            float a1 = (tid >= 1) ? alpha[p][tid - 1] : NEGV;
            float a2 = myallow ? alpha[p][tid - 2] : NEGV;
            alpha[p ^ 1][tid] = lae(lae(a0, a1), a2) + e;
        }
        __syncthreads();
        p ^= 1;
    }

    if (tid == 0) {
        int end = 2 * len_s;
        g_ll[b] = lae(alpha[p][end], alpha[p][end - 1]);
    }
}

// ---------------------------------------------------------------------------
// Kernel 4: finalize loss = -sum_b ll_b
// ---------------------------------------------------------------------------
__global__ void finalize_kernel(float* __restrict__ out) {
    if (threadIdx.x == 0) {
        float s = 0.f;
        for (int b = 0; b < B_DIM; b++) s += g_ll[b];
        out[0] = -s;
    }
}

// ---------------------------------------------------------------------------
// Launch: out = [loss(1), logps(T*B*V)]
// ---------------------------------------------------------------------------
extern "C" void kernel_launch(void* const* d_in, const int* in_sizes, int n_in,
                              void* d_out, int out_size)
{
    const float* ctx  = (const float*)d_in[0];   // [T, B, D]
    const int*   y    = (const int*)  d_in[1];   // [U, B]
    const float* W    = (const float*)d_in[2];   // [D, V]
    const float* bias = (const float*)d_in[3];   // [V]

    float* out   = (float*)d_out;
    float* logps = out + 1;                      // [T, B, V] region

    cudaFuncSetAttribute(gemm_mma_kernel,
                         cudaFuncAttributeMaxDynamicSharedMemorySize, SMEM_TOTAL);

    dim3 gemm_grid((V_DIM + BN - 1) / BN, M_DIM / BM);  // (32, 100)
    gemm_mma_kernel<<<gemm_grid, 256, SMEM_TOTAL>>>(ctx, W, logps);
    logsoftmax_kernel<<<M_DIM, 256>>>(logps, bias);
    ctc_kernel<<<B_DIM, 256>>>(logps, y);
    finalize_kernel<<<1, 32>>>(out);
}

// round 4
// speedup vs baseline: 2.3517x; 1.4714x over previous
#include <cuda_runtime.h>
#include <cuda_bf16.h>
#include <math.h>
#include <stdint.h>

// Problem dims (fixed by the dataset)
#define T_DIM 800
#define B_DIM 16
#define D_DIM 256
#define V_DIM 4001
#define U_DIM 100
#define S_DIM 201              // 2*U+1
#define SP    224              // padded emission stride (>= 224 threads)
#define M_DIM (T_DIM * B_DIM) // 12800
#define NEGV  (-1e30f)

__device__ float g_ll[B_DIM];
__device__ int   g_done = 0;
__device__ float g_emit[M_DIM * SP];   // [T*B][SP] pre-gathered emissions (~11.5 MB)

__device__ __forceinline__ uint32_t smem_u32(const void* p) {
    uint32_t a;
    asm("{ .reg .u64 t; cvta.to.shared.u64 t, %1; cvt.u32.u64 %0, t; }" : "=r"(a) : "l"(p));
    return a;
}

// ---------------------------------------------------------------------------
// Kernel 1: bf16 HMMA GEMM  C[M, V] = A[M, D] * W[D, V] + bias (raw logits)
// CTA tile 128x64, XOR-swizzled smem (96 KB) -> 2 CTA/SM. K pipelined in
// two halves; half-1 fills issued under half-0 MMA shadow.
// ---------------------------------------------------------------------------
#define BM 128
#define BN 64
#define SM_AS 0
#define SM_BS 65536
#define GEMM_SMEM 98304           // 96 KB
#define STG_PITCH 68

// swizzled byte offset inside a [rows][256 bf16] (512B-row) tile
__device__ __forceinline__ uint32_t swz(int row, int kbyte) {
    return (uint32_t)(row * 512 + (kbyte ^ ((row & 7) << 4)));
}

__global__ __launch_bounds__(256, 2) void gemm_mma_kernel(
    const float* __restrict__ A,    // [M, D]
    const float* __restrict__ W,    // [D, V]
    const float* __restrict__ bias, // [V]
    float* __restrict__ C)          // [M, V]
{
    extern __shared__ char smem[];
    char* As = smem + SM_AS;
    char* Bs = smem + SM_BS;

    const int tid  = threadIdx.x;
    const int wid  = tid >> 5;
    const int lane = tid & 31;
    const int bm = blockIdx.y * BM;
    const int bn = blockIdx.x * BN;

    const float2* A2 = reinterpret_cast<const float2*>(A + (size_t)bm * D_DIM);

    // ---- fill half 0 (k in [0,128)) ----
    {
        // A: 128 rows x 64 float2 = 8192 float2 -> 32 per thread
#pragma unroll 8
        for (int i = 0; i < 32; i++) {
            int idx = i * 256 + tid;
            int row = idx >> 6;           // 0..127
            int kp  = idx & 63;           // float2 idx within half (k = 2*kp)
            float2 v = A2[row * 128 + kp];
            __nv_bfloat162 h = __floats2bfloat162_rn(v.x, v.y);
            *reinterpret_cast<uint32_t*>(As + swz(row, kp * 4)) =
                *reinterpret_cast<uint32_t*>(&h);
        }
        // B: 128 k x 64 n = 8192 floats -> 32 per thread
#pragma unroll 8
        for (int i = 0; i < 32; i++) {
            int idx = i * 256 + tid;
            int n = idx & 63;
            int k = idx >> 6;             // 0..127
            int col = bn + n;
            float v = (col < V_DIM) ? __ldg(&W[(size_t)k * V_DIM + col]) : 0.f;
            *reinterpret_cast<__nv_bfloat16*>(Bs + swz(n, k * 2)) = __float2bfloat16(v);
        }
    }
    __syncthreads();

    // warp layout: 4 warps along M, 2 along N
    const int m0 = (wid & 3) * 32;
    const int n0 = (wid >> 2) * 32;

    float acc[2][4][4];
#pragma unroll
    for (int mt = 0; mt < 2; mt++)
#pragma unroll
        for (int nt = 0; nt < 4; nt++)
#pragma unroll
            for (int r = 0; r < 4; r++) acc[mt][nt][r] = 0.f;

    const int a_row  = m0 + (lane & 15);
    const int a_koff = (lane >> 4) * 8;
    const int b_row  = n0 + (lane & 7) + ((lane >> 4) << 3);  // nt-pair base rows
    const int b_koff = ((lane >> 3) & 1) * 8;

    uint32_t as_base = smem_u32(As);
    uint32_t bs_base = smem_u32(Bs);

#define MMA_KSTEP(K0)                                                              \
    {                                                                              \
        uint32_t af[2][4], bfr[2][4];                                              \
        _Pragma("unroll")                                                          \
        for (int mt = 0; mt < 2; mt++) {                                           \
            int r = a_row + mt * 16;                                               \
            uint32_t addr = as_base + swz(r, ((K0) + a_koff) * 2);                 \
            asm volatile("ldmatrix.sync.aligned.m8n8.x4.shared.b16 {%0,%1,%2,%3}, [%4];" \
                         : "=r"(af[mt][0]), "=r"(af[mt][1]), "=r"(af[mt][2]), "=r"(af[mt][3]) \
                         : "r"(addr));                                             \
        }                                                                          \
        _Pragma("unroll")                                                          \
        for (int np = 0; np < 2; np++) {                                           \
            int r = b_row + np * 16;                                               \
            uint32_t addr = bs_base + swz(r, ((K0) + b_koff) * 2);                 \
            asm volatile("ldmatrix.sync.aligned.m8n8.x4.shared.b16 {%0,%1,%2,%3}, [%4];" \
                         : "=r"(bfr[np][0]), "=r"(bfr[np][1]), "=r"(bfr[np][2]), "=r"(bfr[np][3]) \
                         : "r"(addr));                                             \
        }                                                                          \
        _Pragma("unroll")                                                          \
        for (int mt = 0; mt < 2; mt++)                                             \
            _Pragma("unroll")                                                      \
            for (int nt = 0; nt < 4; nt++) {                                       \
                asm volatile(                                                      \
                    "mma.sync.aligned.m16n8k16.row.col.f32.bf16.bf16.f32 "        \
                    "{%0,%1,%2,%3}, {%4,%5,%6,%7}, {%8,%9}, {%0,%1,%2,%3};"       \
                    : "+f"(acc[mt][nt][0]), "+f"(acc[mt][nt][1]),                  \
                      "+f"(acc[mt][nt][2]), "+f"(acc[mt][nt][3])                   \
                    : "r"(af[mt][0]), "r"(af[mt][1]), "r"(af[mt][2]), "r"(af[mt][3]), \
                      "r"(bfr[nt >> 1][(nt & 1) * 2]), "r"(bfr[nt >> 1][(nt & 1) * 2 + 1])); \
            }                                                                      \
    }

    // ---- half-0 MMA with half-1 fills issued under its shadow ----
#pragma unroll
    for (int ks = 0; ks < 8; ks++) {
        // issue half-1 sub-chunk LDGs (4 A float2 + 4 B floats) into regs
        float2 av[4];
        float  bv[4];
#pragma unroll
        for (int j = 0; j < 4; j++) {
            int idx = (ks * 4 + j) * 256 + tid;
            int row = idx >> 6;
            int kp  = idx & 63;
            av[j] = A2[row * 128 + 64 + kp];
            int n = idx & 63;
            int k = idx >> 6;             // 0..127 -> global k = 128 + k
            int col = bn + n;
            bv[j] = (col < V_DIM) ? __ldg(&W[(size_t)(128 + k) * V_DIM + col]) : 0.f;
        }
        MMA_KSTEP(ks * 16)
        // store the fetched sub-chunk into the half-1 smem region
#pragma unroll
        for (int j = 0; j < 4; j++) {
            int idx = (ks * 4 + j) * 256 + tid;
            int row = idx >> 6;
            int kp  = idx & 63;
            __nv_bfloat162 h = __floats2bfloat162_rn(av[j].x, av[j].y);
            *reinterpret_cast<uint32_t*>(As + swz(row, (64 + kp) * 4)) =
                *reinterpret_cast<uint32_t*>(&h);
            int n = idx & 63;
            int k = idx >> 6;
            *reinterpret_cast<__nv_bfloat16*>(Bs + swz(n, (128 + k) * 2)) =
                __float2bfloat16(bv[j]);
        }
    }
    __syncthreads();
    // ---- half-1 MMA ----
#pragma unroll
    for (int ks = 8; ks < 16; ks++) {
        MMA_KSTEP(ks * 16)
    }
    __syncthreads();

    // ---- stage through padded SMEM, then coalesced stores (+bias) ----
    float* stage = reinterpret_cast<float*>(smem);
    {
        const int crow = lane >> 2;
        const int ccol = (lane & 3) * 2;
#pragma unroll
        for (int mt = 0; mt < 2; mt++)
#pragma unroll
            for (int nt = 0; nt < 4; nt++) {
                int r0 = m0 + mt * 16 + crow;
                int c0 = n0 + nt * 8 + ccol;
                *reinterpret_cast<float2*>(&stage[r0 * STG_PITCH + c0]) =
                    make_float2(acc[mt][nt][0], acc[mt][nt][1]);
                *reinterpret_cast<float2*>(&stage[(r0 + 8) * STG_PITCH + c0]) =
                    make_float2(acc[mt][nt][2], acc[mt][nt][3]);
            }
    }
    __syncthreads();
#pragma unroll 8
    for (int i = 0; i < 32; i++) {
        int idx = i * 256 + tid;
        int col = idx & 63;
        int row = idx >> 6;
        int gc = bn + col;
        if (gc < V_DIM)
            C[(size_t)(bm + row) * V_DIM + gc] = stage[row * STG_PITCH + col] + bias[gc];
    }
}

// ---------------------------------------------------------------------------
// Kernel 2: in-place log_softmax per row + CTC emission pre-gather.
// One block per (t, b) row. Warp-shuffle reductions, __expf.
// ---------------------------------------------------------------------------
__global__ __launch_bounds__(256) void logsoftmax_kernel(
    float* __restrict__ logits,      // [M, V] in/out (bias already added)
    const int* __restrict__ y)       // [U, B]
{
    __shared__ float row[4004];
    __shared__ float red[8];

    const int r = blockIdx.x;        // r = t*16 + b
    const int b = r & 15;
    const int tid = threadIdx.x;
    const int lane = tid & 31;
    const int wid = tid >> 5;
    float* p = logits + (size_t)r * V_DIM;

    float m = -INFINITY;
    for (int v = tid; v < V_DIM; v += 256) {
        float x = p[v];
        row[v] = x;
        m = fmaxf(m, x);
    }
#pragma unroll
    for (int s = 16; s > 0; s >>= 1)
        m = fmaxf(m, __shfl_xor_sync(0xffffffffu, m, s));
    if (lane == 0) red[wid] = m;
    __syncthreads();
    if (wid == 0) {
        float t = (lane < 8) ? red[lane] : -INFINITY;
#pragma unroll
        for (int s = 4; s > 0; s >>= 1)
            t = fmaxf(t, __shfl_xor_sync(0xffffffffu, t, s));
        if (lane == 0) red[0] = t;
    }
    __syncthreads();
    float mx = red[0];

    float sum = 0.f;
    for (int v = tid; v < V_DIM; v += 256) sum += __expf(row[v] - mx);
#pragma unroll
    for (int s = 16; s > 0; s >>= 1)
        sum += __shfl_xor_sync(0xffffffffu, sum, s);
    if (lane == 0) red[wid] = sum;
    __syncthreads();
    if (wid == 0) {
        float t = (lane < 8) ? red[lane] : 0.f;
#pragma unroll
        for (int s = 4; s > 0; s >>= 1)
            t += __shfl_xor_sync(0xffffffffu, t, s);
        if (lane == 0) red[0] = t;
    }
    __syncthreads();
    float lse = mx + __logf(red[0]);

    for (int v = tid; v < V_DIM; v += 256) p[v] = row[v] - lse;

    // pre-gather CTC emissions for this (t, b) row
    if (tid < S_DIM) {
        int lab = (tid & 1) ? y[((tid - 1) >> 1) * B_DIM + b] : 0;
        g_emit[r * SP + tid] = row[lab] - lse;
    }
}

// ---------------------------------------------------------------------------
// Kernel 3: CTC forward scan over pre-gathered emissions + finalize.
// One block per batch element (224 threads); deep register prefetch.
// ---------------------------------------------------------------------------
__device__ __forceinline__ float lae(float a, float b) {
    float m = fmaxf(a, b);
    float d = fminf(a, b) - m;            // d <= 0
    return m + __logf(1.0f + __expf(d));
}

__global__ __launch_bounds__(224) void ctc_kernel(
    const int* __restrict__ y,       // [U, B]
    float* __restrict__ out)         // out[0] = loss
{
    const int b = blockIdx.x;
    const int tid = threadIdx.x;

    __shared__ int   ext[S_DIM];
    __shared__ float alpha[2][S_DIM];
    __shared__ int   len_s;

    if (tid == 0) len_s = 0;
    __syncthreads();
    if (tid < U_DIM) {
        if (y[tid * B_DIM + b] != 1) atomicAdd(&len_s, 1);
    }
    if (tid < S_DIM)
        ext[tid] = (tid & 1) ? y[((tid - 1) >> 1) * B_DIM + b] : 0;
    __syncthreads();

    bool myallow = false;
    if (tid < S_DIM && tid >= 2)
        myallow = (ext[tid] != 0) && (ext[tid] != ext[tid - 2]);

    const float* erow = g_emit + b * SP + tid;   // stride 16*SP per t

    if (tid < S_DIM)
        alpha[0][tid] = (tid < 2) ? erow[0] : NEGV;

    // 3-deep emission pipeline (contiguous, coalesced loads)
    float e_cur = erow[(size_t)1 * B_DIM * SP];
    float e_n1  = erow[(size_t)2 * B_DIM * SP];
    float e_n2  = erow[(size_t)3 * B_DIM * SP];
    __syncthreads();

    int p = 0;
    for (int t = 1; t < T_DIM; t++) {
        if (tid < S_DIM) {
            float a0 = alpha[p][tid];
            float a1 = (tid >= 1) ? alpha[p][tid - 1] : NEGV;
            float a2 = myallow ? alpha[p][tid - 2] : NEGV;
            alpha[p ^ 1][tid] = lae(lae(a0, a1), a2) + e_cur;
        }
        e_cur = e_n1;
        e_n1 = e_n2;
        int tn = (t + 4 < T_DIM) ? (t + 4) : (T_DIM - 1);
        e_n2 = erow[(size_t)tn * B_DIM * SP];
        __syncthreads();
        p ^= 1;
    }

    if (tid == 0) {
        int end = 2 * len_s;
        g_ll[b] = lae(alpha[p][end], alpha[p][end - 1]);
        __threadfence();
        int ticket = atomicAdd(&g_done, 1);
        if (ticket == B_DIM - 1) {
            __threadfence();
            float s = 0.f;
#pragma unroll
            for (int i = 0; i < B_DIM; i++) s += g_ll[i];
            out[0] = -s;
            g_done = 0;   // reset for next graph replay
        }
    }
}

// ---------------------------------------------------------------------------
// Launch: out = [loss(1), logps(T*B*V)]
// ---------------------------------------------------------------------------
extern "C" void kernel_launch(void* const* d_in, const int* in_sizes, int n_in,
                              void* d_out, int out_size)
{
    const float* ctx  = (const float*)d_in[0];   // [T, B, D]
    const int*   y    = (const int*)  d_in[1];   // [U, B]
    const float* W    = (const float*)d_in[2];   // [D, V]
    const float* bias = (const float*)d_in[3];   // [V]

    float* out   = (float*)d_out;
    float* logps = out + 1;                      // [T, B, V] region

    cudaFuncSetAttribute(gemm_mma_kernel,
                         cudaFuncAttributeMaxDynamicSharedMemorySize, GEMM_SMEM);

    dim3 gemm_grid((V_DIM + BN - 1) / BN, M_DIM / BM);  // (63, 100)
    gemm_mma_kernel<<<gemm_grid, 256, GEMM_SMEM>>>(ctx, W, bias, logps);
    logsoftmax_kernel<<<M_DIM, 256>>>(logps, y);
    ctc_kernel<<<B_DIM, 224>>>(y, out);
}

// round 6
// speedup vs baseline: 2.5103x; 1.0675x over previous
#include <cuda_runtime.h>
#include <cuda_bf16.h>
#include <math.h>
#include <stdint.h>

// Problem dims (fixed by the dataset)
#define T_DIM 800
#define B_DIM 16
#define D_DIM 256
#define V_DIM 4001
#define VPAD  4096
#define U_DIM 100
#define S_DIM 201              // 2*U+1
#define SP    224              // padded emission stride
#define M_DIM (T_DIM * B_DIM) // 12800
#define NEGV  (-1e30f)

__device__ float g_ll[B_DIM];
__device__ int   g_done = 0;
__device__ float g_emit[M_DIM * SP];                  // pre-gathered emissions
__device__ __nv_bfloat16 g_Abf[M_DIM * D_DIM];        // ctx in bf16
__device__ __nv_bfloat16 g_Wbf[VPAD * D_DIM];         // W^T in bf16 [v][k], zero-padded

__device__ __forceinline__ uint32_t smem_u32(const void* p) {
    uint32_t a;
    asm("{ .reg .u64 t; cvta.to.shared.u64 t, %1; cvt.u32.u64 %0, t; }" : "=r"(a) : "l"(p));
    return a;
}
__device__ __forceinline__ void cp16(uint32_t dst, const void* src) {
    asm volatile("cp.async.cg.shared.global [%0], [%1], 16;" :: "r"(dst), "l"(src));
}

// ---------------------------------------------------------------------------
// Kernel 0a: ctx fp32 -> bf16
// ---------------------------------------------------------------------------
__global__ __launch_bounds__(256) void conv_a_kernel(const float* __restrict__ A) {
    int i = blockIdx.x * 256 + threadIdx.x;          // float4 index, grid covers M*D/4
    float4 v = reinterpret_cast<const float4*>(A)[i];
    __nv_bfloat162 h0 = __floats2bfloat162_rn(v.x, v.y);
    __nv_bfloat162 h1 = __floats2bfloat162_rn(v.z, v.w);
    uint32_t* out = reinterpret_cast<uint32_t*>(g_Abf);
    out[i * 2]     = *reinterpret_cast<uint32_t*>(&h0);
    out[i * 2 + 1] = *reinterpret_cast<uint32_t*>(&h1);
}

// ---------------------------------------------------------------------------
// Kernel 0b: W [k][v] fp32 -> g_Wbf [v][k] bf16 (tiled transpose, zero pad)
// ---------------------------------------------------------------------------
__global__ __launch_bounds__(256) void conv_w_kernel(const float* __restrict__ W) {
    __shared__ float tile[32][33];
    int v0 = blockIdx.x * 32;   // 128 blocks
    int k0 = blockIdx.y * 32;   // 8 blocks
    int tx = threadIdx.x & 31;
    int ty = threadIdx.x >> 5;  // 0..7
#pragma unroll
    for (int j = 0; j < 32; j += 8) {
        int k = k0 + ty + j, v = v0 + tx;
        tile[ty + j][tx] = (v < V_DIM) ? W[(size_t)k * V_DIM + v] : 0.f;
    }
    __syncthreads();
#pragma unroll
    for (int j = 0; j < 32; j += 8) {
        int v = v0 + ty + j, k = k0 + tx;
        g_Wbf[(size_t)v * D_DIM + k] = __float2bfloat16(tile[tx][ty + j]);
    }
}

// ---------------------------------------------------------------------------
// Kernel 1: bf16 HMMA GEMM  C[M, V] = A * W + bias.
// CTA 128x128, 3-stage cp.async pipeline over K chunks of 64, warp tile 64x32.
// ---------------------------------------------------------------------------
#define BM 128
#define BN 128
#define STAGE_BYTES 32768           // A 16KB + B 16KB
#define GEMM_SMEM 98304             // 3 stages
#define STG_PITCH 132

__device__ __forceinline__ void issue_stage(uint32_t sbase, int s, int kc,
                                            int bm, int bn, int tid) {
    uint32_t stage = sbase + s * STAGE_BYTES;
#pragma unroll
    for (int i = 0; i < 4; i++) {                    // A: 128 rows x 8 chunks
        int c = i * 256 + tid;
        int row = c >> 3, ch = c & 7;
        uint32_t dst = stage + row * 128 + ((ch * 16) ^ ((row & 7) << 4));
        cp16(dst, &g_Abf[(size_t)(bm + row) * D_DIM + kc * 64 + ch * 8]);
    }
#pragma unroll
    for (int i = 0; i < 4; i++) {                    // B: 128 rows x 8 chunks (padded, no guard)
        int c = i * 256 + tid;
        int row = c >> 3, ch = c & 7;
        uint32_t dst = stage + 16384 + row * 128 + ((ch * 16) ^ ((row & 7) << 4));
        cp16(dst, &g_Wbf[(size_t)(bn + row) * D_DIM + kc * 64 + ch * 8]);
    }
}

__global__ __launch_bounds__(256, 2) void gemm_mma_kernel(
    const float* __restrict__ bias,  // [V]
    float* __restrict__ C)           // [M, V]
{
    extern __shared__ char smem[];
    uint32_t sbase = smem_u32(smem);

    const int tid  = threadIdx.x;
    const int wid  = tid >> 5;
    const int lane = tid & 31;
    const int bm = blockIdx.y * BM;
    const int bn = blockIdx.x * BN;

    // warp layout: 2 warps along M (64 each), 4 along N (32 each)
    const int m0 = (wid & 1) * 64;
    const int n0 = (wid >> 1) * 32;

    float acc[4][4][4];
#pragma unroll
    for (int mt = 0; mt < 4; mt++)
#pragma unroll
        for (int nt = 0; nt < 4; nt++)
#pragma unroll
            for (int r = 0; r < 4; r++) acc[mt][nt][r] = 0.f;

    const int a_row  = m0 + (lane & 15);
    const int a_kb   = (lane >> 4) * 16;                        // byte sub-offset
    const int b_row  = n0 + (lane & 7) + ((lane >> 4) << 3);
    const int b_kb   = ((lane >> 3) & 1) * 16;

    issue_stage(sbase, 0, 0, bm, bn, tid);
    asm volatile("cp.async.commit_group;");
    issue_stage(sbase, 1, 1, bm, bn, tid);
    asm volatile("cp.async.commit_group;");

#pragma unroll
    for (int kc = 0; kc < 4; kc++) {
        asm volatile("cp.async.wait_group 1;");
        __syncthreads();
        if (kc + 2 < 4) issue_stage(sbase, (kc + 2) % 3, kc + 2, bm, bn, tid);
        asm volatile("cp.async.commit_group;");

        uint32_t abase = sbase + (kc % 3) * STAGE_BYTES;
        uint32_t bbase = abase + 16384;
#pragma unroll
        for (int kk = 0; kk < 4; kk++) {
            uint32_t af[4][4], bfr[2][4];
#pragma unroll
            for (int mt = 0; mt < 4; mt++) {
                int r = a_row + mt * 16;
                uint32_t addr = abase + r * 128 + ((kk * 32 + a_kb) ^ ((r & 7) << 4));
                asm volatile("ldmatrix.sync.aligned.m8n8.x4.shared.b16 {%0,%1,%2,%3}, [%4];"
                             : "=r"(af[mt][0]), "=r"(af[mt][1]), "=r"(af[mt][2]), "=r"(af[mt][3])
                             : "r"(addr));
            }
#pragma unroll
            for (int np = 0; np < 2; np++) {
                int r = b_row + np * 16;
                uint32_t addr = bbase + r * 128 + ((kk * 32 + b_kb) ^ ((r & 7) << 4));
                asm volatile("ldmatrix.sync.aligned.m8n8.x4.shared.b16 {%0,%1,%2,%3}, [%4];"
                             : "=r"(bfr[np][0]), "=r"(bfr[np][1]), "=r"(bfr[np][2]), "=r"(bfr[np][3])
                             : "r"(addr));
            }
#pragma unroll
            for (int mt = 0; mt < 4; mt++)
#pragma unroll
                for (int nt = 0; nt < 4; nt++) {
                    asm volatile(
                        "mma.sync.aligned.m16n8k16.row.col.f32.bf16.bf16.f32 "
                        "{%0,%1,%2,%3}, {%4,%5,%6,%7}, {%8,%9}, {%0,%1,%2,%3};"
                        : "+f"(acc[mt][nt][0]), "+f"(acc[mt][nt][1]),
                          "+f"(acc[mt][nt][2]), "+f"(acc[mt][nt][3])
                        : "r"(af[mt][0]), "r"(af[mt][1]), "r"(af[mt][2]), "r"(af[mt][3]),
                          "r"(bfr[nt >> 1][(nt & 1) * 2]), "r"(bfr[nt >> 1][(nt & 1) * 2 + 1]));
                }
        }
    }
    __syncthreads();

    // ---- epilogue: stage in smem, coalesced stores with bias ----
    float* stage = reinterpret_cast<float*>(smem);
    {
        const int crow = lane >> 2;
        const int ccol = (lane & 3) * 2;
#pragma unroll
        for (int mt = 0; mt < 4; mt++)
#pragma unroll
            for (int nt = 0; nt < 4; nt++) {
                int r0 = m0 + mt * 16 + crow;
                int c0 = n0 + nt * 8 + ccol;
                *reinterpret_cast<float2*>(&stage[r0 * STG_PITCH + c0]) =
                    make_float2(acc[mt][nt][0], acc[mt][nt][1]);
                *reinterpret_cast<float2*>(&stage[(r0 + 8) * STG_PITCH + c0]) =
                    make_float2(acc[mt][nt][2], acc[mt][nt][3]);
            }
    }
    __syncthreads();
#pragma unroll 8
    for (int i = 0; i < 64; i++) {
        int idx = i * 256 + tid;
        int col = idx & 127;
        int row = idx >> 7;
        int gc = bn + col;
        if (gc < V_DIM)
            C[(size_t)(bm + row) * V_DIM + gc] = stage[row * STG_PITCH + col] + bias[gc];
    }
}

// ---------------------------------------------------------------------------
// Kernel 2: register-resident log_softmax + CTC emission pre-gather.
// One block (256 thr) per (t, b) row; row held in 16 regs/thread.
// ---------------------------------------------------------------------------
__global__ __launch_bounds__(256) void logsoftmax_kernel(
    float* __restrict__ logits,      // [M, V] in/out (bias already added)
    const int* __restrict__ y)       // [U, B]
{
    __shared__ float red[8];

    const int r = blockIdx.x;        // r = t*16 + b
    const int b = r & 15;
    const int tid = threadIdx.x;
    const int lane = tid & 31;
    const int wid = tid >> 5;
    float* p = logits + (size_t)r * V_DIM;

    // early raw-logit gather for the CTC emission (reads before any writes)
    float e_raw = 0.f;
    int lab = 0;
    if (tid < S_DIM) {
        lab = (tid & 1) ? y[((tid - 1) >> 1) * B_DIM + b] : 0;
        e_raw = p[lab];
    }

    float x[16];
    float m = -INFINITY;
#pragma unroll
    for (int i = 0; i < 16; i++) {
        int v = tid + i * 256;
        x[i] = (v < V_DIM) ? p[v] : -INFINITY;
        m = fmaxf(m, x[i]);
    }
#pragma unroll
    for (int s = 16; s > 0; s >>= 1)
        m = fmaxf(m, __shfl_xor_sync(0xffffffffu, m, s));
    if (lane == 0) red[wid] = m;
    __syncthreads();
    if (wid == 0) {
        float t = (lane < 8) ? red[lane] : -INFINITY;
#pragma unroll
        for (int s = 4; s > 0; s >>= 1)
            t = fmaxf(t, __shfl_xor_sync(0xffffffffu, t, s));
        if (lane == 0) red[0] = t;
    }
    __syncthreads();
    float mx = red[0];

    float sum = 0.f;
#pragma unroll
    for (int i = 0; i < 16; i++) sum += __expf(x[i] - mx);   // exp(-inf)=0 for pad
#pragma unroll
    for (int s = 16; s > 0; s >>= 1)
        sum += __shfl_xor_sync(0xffffffffu, sum, s);
    if (lane == 0) red[wid] = sum;
    __syncthreads();
    if (wid == 0) {
        float t = (lane < 8) ? red[lane] : 0.f;
#pragma unroll
        for (int s = 4; s > 0; s >>= 1)
            t += __shfl_xor_sync(0xffffffffu, t, s);
        if (lane == 0) red[0] = t;
    }
    __syncthreads();
    float lse = mx + __logf(red[0]);

    if (tid < S_DIM) g_emit[r * SP + tid] = e_raw - lse;

#pragma unroll
    for (int i = 0; i < 16; i++) {
        int v = tid + i * 256;
        if (v < V_DIM) p[v] = x[i] - lse;
    }
}

// ---------------------------------------------------------------------------
// Kernel 3: CTC forward scan over pre-gathered emissions + finalize.
// ---------------------------------------------------------------------------
__device__ __forceinline__ float lae(float a, float b) {
    float m = fmaxf(a, b);
    float d = fminf(a, b) - m;            // d <= 0
    return m + __logf(1.0f + __expf(d));
}

__global__ __launch_bounds__(224) void ctc_kernel(
    const int* __restrict__ y,       // [U, B]
    float* __restrict__ out)         // out[0] = loss
{
    const int b = blockIdx.x;
    const int tid = threadIdx.x;

    __shared__ int   ext[S_DIM];
    __shared__ float alpha[2][S_DIM];
    __shared__ int   len_s;

    if (tid == 0) len_s = 0;
    __syncthreads();
    if (tid < U_DIM) {
        if (y[tid * B_DIM + b] != 1) atomicAdd(&len_s, 1);
    }
    if (tid < S_DIM)
        ext[tid] = (tid & 1) ? y[((tid - 1) >> 1) * B_DIM + b] : 0;
    __syncthreads();

    bool myallow = false;
    if (tid < S_DIM && tid >= 2)
        myallow = (ext[tid] != 0) && (ext[tid] != ext[tid - 2]);

    const float* erow = g_emit + b * SP + tid;

    if (tid < S_DIM)
        alpha[0][tid] = (tid < 2) ? erow[0] : NEGV;

    float e_cur = erow[(size_t)1 * B_DIM * SP];
    float e_n1  = erow[(size_t)2 * B_DIM * SP];
    float e_n2  = erow[(size_t)3 * B_DIM * SP];
    __syncthreads();

    int p = 0;
    for (int t = 1; t < T_DIM; t++) {
        if (tid < S_DIM) {
            float a0 = alpha[p][tid];
            float a1 = (tid >= 1) ? alpha[p][tid - 1] : NEGV;
            float a2 = myallow ? alpha[p][tid - 2] : NEGV;
            alpha[p ^ 1][tid] = lae(lae(a0, a1), a2) + e_cur;
        }
        e_cur = e_n1;
        e_n1 = e_n2;
        int tn = (t + 4 < T_DIM) ? (t + 4) : (T_DIM - 1);
        e_n2 = erow[(size_t)tn * B_DIM * SP];
        __syncthreads();
        p ^= 1;
    }

    if (tid == 0) {
        int end = 2 * len_s;
        g_ll[b] = lae(alpha[p][end], alpha[p][end - 1]);
        __threadfence();
        int ticket = atomicAdd(&g_done, 1);
        if (ticket == B_DIM - 1) {
            __threadfence();
            float s = 0.f;
#pragma unroll
            for (int i = 0; i < B_DIM; i++) s += g_ll[i];
            out[0] = -s;
            g_done = 0;   // reset for next graph replay
        }
    }
}

// ---------------------------------------------------------------------------
// Launch: out = [loss(1), logps(T*B*V)]
// ---------------------------------------------------------------------------
extern "C" void kernel_launch(void* const* d_in, const int* in_sizes, int n_in,
                              void* d_out, int out_size)
{
    const float* ctx  = (const float*)d_in[0];   // [T, B, D]
    const int*   y    = (const int*)  d_in[1];   // [U, B]
    const float* W    = (const float*)d_in[2];   // [D, V]
    const float* bias = (const float*)d_in[3];   // [V]

    float* out   = (float*)d_out;
    float* logps = out + 1;                      // [T, B, V] region

    cudaFuncSetAttribute(gemm_mma_kernel,
                         cudaFuncAttributeMaxDynamicSharedMemorySize, GEMM_SMEM);

    conv_a_kernel<<<M_DIM * D_DIM / 4 / 256, 256>>>(ctx);
    conv_w_kernel<<<dim3(VPAD / 32, D_DIM / 32), 256>>>(W);

    dim3 gemm_grid(VPAD / BN, M_DIM / BM);       // (32, 100)
    gemm_mma_kernel<<<gemm_grid, 256, GEMM_SMEM>>>(bias, logps);
    logsoftmax_kernel<<<M_DIM, 256>>>(logps, y);
    ctc_kernel<<<B_DIM, 224>>>(y, out);
}

// round 8
// speedup vs baseline: 3.0359x; 1.2094x over previous
#include <cuda_runtime.h>
#include <cuda_bf16.h>
#include <math.h>
#include <stdint.h>

// Problem dims (fixed by the dataset)
#define T_DIM 800
#define B_DIM 16
#define D_DIM 256
#define V_DIM 4001
#define VPAD  4096
#define U_DIM 100
#define S_DIM 201              // 2*U+1
#define SP    224              // padded emission stride
#define M_DIM (T_DIM * B_DIM) // 12800
#define NEGV  (-1e30f)

__device__ float g_ll[B_DIM];
__device__ int   g_done = 0;
__device__ float g_emit[M_DIM * SP];                  // pre-gathered emissions
__device__ __nv_bfloat16 g_Abf[M_DIM * D_DIM];        // ctx in bf16
__device__ __nv_bfloat16 g_Wbf[VPAD * D_DIM];         // W^T in bf16 [v][k], zero-padded

__device__ __forceinline__ uint32_t smem_u32(const void* p) {
    uint32_t a;
    asm("{ .reg .u64 t; cvta.to.shared.u64 t, %1; cvt.u32.u64 %0, t; }" : "=r"(a) : "l"(p));
    return a;
}
__device__ __forceinline__ void cp16(uint32_t dst, const void* src) {
    asm volatile("cp.async.cg.shared.global [%0], [%1], 16;" :: "r"(dst), "l"(src));
}

// ---------------------------------------------------------------------------
// Kernel 0: fused input conversion.
//   blocks [0, 3200):      ctx fp32 -> g_Abf bf16
//   blocks [3200, 4224):   W [k][v] fp32 -> g_Wbf [v][k] bf16 (transpose+pad)
// ---------------------------------------------------------------------------
#define CONV_A_BLKS (M_DIM * D_DIM / 4 / 256)   // 3200
#define CONV_W_BLKS ((VPAD / 32) * (D_DIM / 32)) // 1024

__global__ __launch_bounds__(256) void conv_kernel(
    const float* __restrict__ A, const float* __restrict__ W)
{
    if (blockIdx.x < CONV_A_BLKS) {
        int i = blockIdx.x * 256 + threadIdx.x;          // float4 index
        float4 v = reinterpret_cast<const float4*>(A)[i];
        __nv_bfloat162 h0 = __floats2bfloat162_rn(v.x, v.y);
        __nv_bfloat162 h1 = __floats2bfloat162_rn(v.z, v.w);
        uint32_t* out = reinterpret_cast<uint32_t*>(g_Abf);
        out[i * 2]     = *reinterpret_cast<uint32_t*>(&h0);
        out[i * 2 + 1] = *reinterpret_cast<uint32_t*>(&h1);
    } else {
        __shared__ float tile[32][33];
        int bid = blockIdx.x - CONV_A_BLKS;
        int v0 = (bid & 127) * 32;
        int k0 = (bid >> 7) * 32;
        int tx = threadIdx.x & 31;
        int ty = threadIdx.x >> 5;  // 0..7
#pragma unroll
        for (int j = 0; j < 32; j += 8) {
            int k = k0 + ty + j, v = v0 + tx;
            tile[ty + j][tx] = (v < V_DIM) ? W[(size_t)k * V_DIM + v] : 0.f;
        }
        __syncthreads();
#pragma unroll
        for (int j = 0; j < 32; j += 8) {
            int v = v0 + ty + j, k = k0 + tx;
            g_Wbf[(size_t)v * D_DIM + k] = __float2bfloat16(tile[tx][ty + j]);
        }
    }
}

// ---------------------------------------------------------------------------
// Kernel 1: bf16 HMMA GEMM  C[M, V] = A * W + bias.
// CTA 128x128, 3-stage cp.async pipeline over K chunks of 64, warp tile 64x32.
// ---------------------------------------------------------------------------
#define BM 128
#define BN 128
#define STAGE_BYTES 32768           // A 16KB + B 16KB
#define GEMM_SMEM 98304             // 3 stages
#define STG_PITCH 132

__device__ __forceinline__ void issue_stage(uint32_t sbase, int s, int kc,
                                            int bm, int bn, int tid) {
    uint32_t stage = sbase + s * STAGE_BYTES;
#pragma unroll
    for (int i = 0; i < 4; i++) {                    // A: 128 rows x 8 chunks
        int c = i * 256 + tid;
        int row = c >> 3, ch = c & 7;
        uint32_t dst = stage + row * 128 + ((ch * 16) ^ ((row & 7) << 4));
        cp16(dst, &g_Abf[(size_t)(bm + row) * D_DIM + kc * 64 + ch * 8]);
    }
#pragma unroll
    for (int i = 0; i < 4; i++) {                    // B: 128 rows x 8 chunks (padded, no guard)
        int c = i * 256 + tid;
        int row = c >> 3, ch = c & 7;
        uint32_t dst = stage + 16384 + row * 128 + ((ch * 16) ^ ((row & 7) << 4));
        cp16(dst, &g_Wbf[(size_t)(bn + row) * D_DIM + kc * 64 + ch * 8]);
    }
}

__global__ __launch_bounds__(256, 2) void gemm_mma_kernel(
    const float* __restrict__ bias,  // [V]
    float* __restrict__ C)           // [M, V]
{
    extern __shared__ char smem[];
    uint32_t sbase = smem_u32(smem);

    const int tid  = threadIdx.x;
    const int wid  = tid >> 5;
    const int lane = tid & 31;
    const int bm = blockIdx.y * BM;
    const int bn = blockIdx.x * BN;

    // warp layout: 2 warps along M (64 each), 4 along N (32 each)
    const int m0 = (wid & 1) * 64;
    const int n0 = (wid >> 1) * 32;

    float acc[4][4][4];
#pragma unroll
    for (int mt = 0; mt < 4; mt++)
#pragma unroll
        for (int nt = 0; nt < 4; nt++)
#pragma unroll
            for (int r = 0; r < 4; r++) acc[mt][nt][r] = 0.f;

    const int a_row  = m0 + (lane & 15);
    const int a_kb   = (lane >> 4) * 16;                        // byte sub-offset
    const int b_row  = n0 + (lane & 7) + ((lane >> 4) << 3);
    const int b_kb   = ((lane >> 3) & 1) * 16;

    issue_stage(sbase, 0, 0, bm, bn, tid);
    asm volatile("cp.async.commit_group;");
    issue_stage(sbase, 1, 1, bm, bn, tid);
    asm volatile("cp.async.commit_group;");

#pragma unroll
    for (int kc = 0; kc < 4; kc++) {
        asm volatile("cp.async.wait_group 1;");
        __syncthreads();
        if (kc < 2) {
            issue_stage(sbase, (kc + 2) % 3, kc + 2, bm, bn, tid);
        }
        asm volatile("cp.async.commit_group;");

        uint32_t abase = sbase + (kc % 3) * STAGE_BYTES;
        uint32_t bbase = abase + 16384;
#pragma unroll
        for (int kk = 0; kk < 4; kk++) {
            uint32_t af[4][4], bfr[2][4];
#pragma unroll
            for (int mt = 0; mt < 4; mt++) {
                int r = a_row + mt * 16;
                uint32_t addr = abase + r * 128 + ((kk * 32 + a_kb) ^ ((r & 7) << 4));
                asm volatile("ldmatrix.sync.aligned.m8n8.x4.shared.b16 {%0,%1,%2,%3}, [%4];"
                             : "=r"(af[mt][0]), "=r"(af[mt][1]), "=r"(af[mt][2]), "=r"(af[mt][3])
                             : "r"(addr));
            }
#pragma unroll
            for (int np = 0; np < 2; np++) {
                int r = b_row + np * 16;
                uint32_t addr = bbase + r * 128 + ((kk * 32 + b_kb) ^ ((r & 7) << 4));
                asm volatile("ldmatrix.sync.aligned.m8n8.x4.shared.b16 {%0,%1,%2,%3}, [%4];"
                             : "=r"(bfr[np][0]), "=r"(bfr[np][1]), "=r"(bfr[np][2]), "=r"(bfr[np][3])
                             : "r"(addr));
            }
#pragma unroll
            for (int mt = 0; mt < 4; mt++)
#pragma unroll
                for (int nt = 0; nt < 4; nt++) {
                    asm volatile(
                        "mma.sync.aligned.m16n8k16.row.col.f32.bf16.bf16.f32 "
                        "{%0,%1,%2,%3}, {%4,%5,%6,%7}, {%8,%9}, {%0,%1,%2,%3};"
                        : "+f"(acc[mt][nt][0]), "+f"(acc[mt][nt][1]),
                          "+f"(acc[mt][nt][2]), "+f"(acc[mt][nt][3])
                        : "r"(af[mt][0]), "r"(af[mt][1]), "r"(af[mt][2]), "r"(af[mt][3]),
                          "r"(bfr[nt >> 1][(nt & 1) * 2]), "r"(bfr[nt >> 1][(nt & 1) * 2 + 1]));
                }
        }
    }
    __syncthreads();

    // ---- epilogue: stage in smem, coalesced stores with bias ----
    float* stage = reinterpret_cast<float*>(smem);
    {
        const int crow = lane >> 2;
        const int ccol = (lane & 3) * 2;
#pragma unroll
        for (int mt = 0; mt < 4; mt++)
#pragma unroll
            for (int nt = 0; nt < 4; nt++) {
                int r0 = m0 + mt * 16 + crow;
                int c0 = n0 + nt * 8 + ccol;
                *reinterpret_cast<float2*>(&stage[r0 * STG_PITCH + c0]) =
                    make_float2(acc[mt][nt][0], acc[mt][nt][1]);
                *reinterpret_cast<float2*>(&stage[(r0 + 8) * STG_PITCH + c0]) =
                    make_float2(acc[mt][nt][2], acc[mt][nt][3]);
            }
    }
    __syncthreads();
#pragma unroll 8
    for (int i = 0; i < 64; i++) {
        int idx = i * 256 + tid;
        int col = idx & 127;
        int row = idx >> 7;
        int gc = bn + col;
        if (gc < V_DIM)
            C[(size_t)(bm + row) * V_DIM + gc] = stage[row * STG_PITCH + col] + bias[gc];
    }
}

// ---------------------------------------------------------------------------
// Kernel 2: register-resident log_softmax + CTC emission pre-gather.
// ---------------------------------------------------------------------------
__global__ __launch_bounds__(256) void logsoftmax_kernel(
    float* __restrict__ logits,      // [M, V] in/out (bias already added)
    const int* __restrict__ y)       // [U, B]
{
    __shared__ float red[8];

    const int r = blockIdx.x;        // r = t*16 + b
    const int b = r & 15;
    const int tid = threadIdx.x;
    const int lane = tid & 31;
    const int wid = tid >> 5;
    float* p = logits + (size_t)r * V_DIM;

    // early raw-logit gather for the CTC emission (reads before any writes)
    float e_raw = 0.f;
    if (tid < S_DIM) {
        int lab = (tid & 1) ? y[((tid - 1) >> 1) * B_DIM + b] : 0;
        e_raw = p[lab];
    }

    float x[16];
    float m = -INFINITY;
#pragma unroll
    for (int i = 0; i < 16; i++) {
        int v = tid + i * 256;
        x[i] = (v < V_DIM) ? p[v] : -INFINITY;
        m = fmaxf(m, x[i]);
    }
#pragma unroll
    for (int s = 16; s > 0; s >>= 1)
        m = fmaxf(m, __shfl_xor_sync(0xffffffffu, m, s));
    if (lane == 0) red[wid] = m;
    __syncthreads();
    if (wid == 0) {
        float t = (lane < 8) ? red[lane] : -INFINITY;
#pragma unroll
        for (int s = 4; s > 0; s >>= 1)
            t = fmaxf(t, __shfl_xor_sync(0xffffffffu, t, s));
        if (lane == 0) red[0] = t;
    }
    __syncthreads();
    float mx = red[0];

    float sum = 0.f;
#pragma unroll
    for (int i = 0; i < 16; i++) sum += __expf(x[i] - mx);   // exp(-inf)=0 for pad
#pragma unroll
    for (int s = 16; s > 0; s >>= 1)
        sum += __shfl_xor_sync(0xffffffffu, sum, s);
    if (lane == 0) red[wid] = sum;
    __syncthreads();
    if (wid == 0) {
        float t = (lane < 8) ? red[lane] : 0.f;
#pragma unroll
        for (int s = 4; s > 0; s >>= 1)
            t += __shfl_xor_sync(0xffffffffu, t, s);
        if (lane == 0) red[0] = t;
    }
    __syncthreads();
    float lse = mx + __logf(red[0]);

    if (tid < S_DIM) g_emit[r * SP + tid] = e_raw - lse;

#pragma unroll
    for (int i = 0; i < 16; i++) {
        int v = tid + i * 256;
        if (v < V_DIM) p[v] = x[i] - lse;
    }
}

// ---------------------------------------------------------------------------
// Kernel 3: CTC forward scan over pre-gathered emissions + finalize.
// 3-way flat logsumexp: parallel exps -> shorter critical path.
// ---------------------------------------------------------------------------
__device__ __forceinline__ float lae(float a, float b) {
    float m = fmaxf(a, b);
    float d = fminf(a, b) - m;
    return m + __logf(1.0f + __expf(d));
}
__device__ __forceinline__ float lae3(float a, float b, float c) {
    float m = fmaxf(fmaxf(a, b), c);
    float s = __expf(a - m) + __expf(b - m) + __expf(c - m);
    return m + __logf(s);
}

__global__ __launch_bounds__(224) void ctc_kernel(
    const int* __restrict__ y,       // [U, B]
    float* __restrict__ out)         // out[0] = loss
{
    const int b = blockIdx.x;
    const int tid = threadIdx.x;

    __shared__ int   ext[S_DIM];
    __shared__ float alpha[2][S_DIM];
    __shared__ int   len_s;

    if (tid == 0) len_s = 0;
    __syncthreads();
    if (tid < U_DIM) {
        if (y[tid * B_DIM + b] != 1) atomicAdd(&len_s, 1);
    }
    if (tid < S_DIM)
        ext[tid] = (tid & 1) ? y[((tid - 1) >> 1) * B_DIM + b] : 0;
    __syncthreads();

    bool myallow = false;
    if (tid < S_DIM && tid >= 2)
        myallow = (ext[tid] != 0) && (ext[tid] != ext[tid - 2]);

    const float* erow = g_emit + b * SP + tid;

    if (tid < S_DIM)
        alpha[0][tid] = (tid < 2) ? erow[0] : NEGV;

    float e_cur = erow[(size_t)1 * B_DIM * SP];
    float e_n1  = erow[(size_t)2 * B_DIM * SP];
    float e_n2  = erow[(size_t)3 * B_DIM * SP];
    __syncthreads();

    int p = 0;
    for (int t = 1; t < T_DIM; t++) {
        if (tid < S_DIM) {
            float a0 = alpha[p][tid];
            float a1 = (tid >= 1) ? alpha[p][tid - 1] : NEGV;
            float a2 = myallow ? alpha[p][tid - 2] : NEGV;
            alpha[p ^ 1][tid] = lae3(a0, a1, a2) + e_cur;
        }
        e_cur = e_n1;
        e_n1 = e_n2;
        int tn = (t + 4 < T_DIM) ? (t + 4) : (T_DIM - 1);
        e_n2 = erow[(size_t)tn * B_DIM * SP];
        __syncthreads();
        p ^= 1;
    }

    if (tid == 0) {
        int end = 2 * len_s;
        g_ll[b] = lae(alpha[p][end], alpha[p][end - 1]);
        __threadfence();
        int ticket = atomicAdd(&g_done, 1);
        if (ticket == B_DIM - 1) {
            __threadfence();
            float s = 0.f;
#pragma unroll
            for (int i = 0; i < B_DIM; i++) s += g_ll[i];
            out[0] = -s;
            g_done = 0;   // reset for next graph replay
        }
    }
}

// ---------------------------------------------------------------------------
// Launch: out = [loss(1), logps(T*B*V)]
// ---------------------------------------------------------------------------
extern "C" void kernel_launch(void* const* d_in, const int* in_sizes, int n_in,
                              void* d_out, int out_size)
{
    const float* ctx  = (const float*)d_in[0];   // [T, B, D]
    const int*   y    = (const int*)  d_in[1];   // [U, B]
    const float* W    = (const float*)d_in[2];   // [D, V]
    const float* bias = (const float*)d_in[3];   // [V]

    float* out   = (float*)d_out;
    float* logps = out + 1;                      // [T, B, V] region

    cudaFuncSetAttribute(gemm_mma_kernel,
                         cudaFuncAttributeMaxDynamicSharedMemorySize, GEMM_SMEM);

    conv_kernel<<<CONV_A_BLKS + CONV_W_BLKS, 256>>>(ctx, W);

    dim3 gemm_grid(VPAD / BN, M_DIM / BM);       // (32, 100)
    gemm_mma_kernel<<<gemm_grid, 256, GEMM_SMEM>>>(bias, logps);
    logsoftmax_kernel<<<M_DIM, 256>>>(logps, y);
    ctc_kernel<<<B_DIM, 224>>>(y, out);
}

// round 14
// speedup vs baseline: 3.5722x; 1.1767x over previous
#include <cuda_runtime.h>
#include <cuda_bf16.h>
#include <math.h>
#include <stdint.h>

// Problem dims (fixed by the dataset)
#define T_DIM 800
#define B_DIM 16
#define D_DIM 256
#define V_DIM 4001
#define VPAD  4096
#define U_DIM 100
#define S_DIM 201              // 2*U+1
#define SP    224              // padded emission stride
#define M_DIM (T_DIM * B_DIM) // 12800

__device__ float g_ll[B_DIM];
__device__ int   g_done = 0;
__device__ float g_emit[M_DIM * SP];                  // emission PROBABILITIES (pads stay 0)
__device__ __nv_bfloat16 g_Abf[M_DIM * D_DIM];        // ctx in bf16
__device__ __nv_bfloat16 g_Wbf[VPAD * D_DIM];         // W^T in bf16 [v][k], zero-padded

__device__ __forceinline__ uint32_t smem_u32(const void* p) {
    uint32_t a;
    asm("{ .reg .u64 t; cvta.to.shared.u64 t, %1; cvt.u32.u64 %0, t; }" : "=r"(a) : "l"(p));
    return a;
}
__device__ __forceinline__ void cp16(uint32_t dst, const void* src) {
    asm volatile("cp.async.cg.shared.global [%0], [%1], 16;" :: "r"(dst), "l"(src));
}

// ---------------------------------------------------------------------------
// Kernel 0: fused input conversion.
// ---------------------------------------------------------------------------
#define CONV_A_BLKS (M_DIM * D_DIM / 4 / 256)   // 3200
#define CONV_W_BLKS ((VPAD / 32) * (D_DIM / 32)) // 1024

__global__ __launch_bounds__(256) void conv_kernel(
    const float* __restrict__ A, const float* __restrict__ W)
{
    if (blockIdx.x < CONV_A_BLKS) {
        int i = blockIdx.x * 256 + threadIdx.x;          // float4 index
        float4 v = reinterpret_cast<const float4*>(A)[i];
        __nv_bfloat162 h0 = __floats2bfloat162_rn(v.x, v.y);
        __nv_bfloat162 h1 = __floats2bfloat162_rn(v.z, v.w);
        uint32_t* out = reinterpret_cast<uint32_t*>(g_Abf);
        out[i * 2]     = *reinterpret_cast<uint32_t*>(&h0);
        out[i * 2 + 1] = *reinterpret_cast<uint32_t*>(&h1);
    } else {
        __shared__ float tile[32][33];
        int bid = blockIdx.x - CONV_A_BLKS;
        int v0 = (bid & 127) * 32;
        int k0 = (bid >> 7) * 32;
        int tx = threadIdx.x & 31;
        int ty = threadIdx.x >> 5;  // 0..7
#pragma unroll
        for (int j = 0; j < 32; j += 8) {
            int k = k0 + ty + j, v = v0 + tx;
            tile[ty + j][tx] = (v < V_DIM) ? W[(size_t)k * V_DIM + v] : 0.f;
        }
        __syncthreads();
#pragma unroll
        for (int j = 0; j < 32; j += 8) {
            int v = v0 + ty + j, k = k0 + tx;
            g_Wbf[(size_t)v * D_DIM + k] = __float2bfloat16(tile[tx][ty + j]);
        }
    }
}

// ---------------------------------------------------------------------------
// Kernel 1: bf16 HMMA GEMM  C[M, V] = A * W + bias.
// CTA 128x128, 3-stage cp.async pipeline over K chunks of 64, warp tile 64x32.
// ---------------------------------------------------------------------------
#define BM 128
#define BN 128
#define STAGE_BYTES 32768           // A 16KB + B 16KB
#define GEMM_SMEM 98304             // 3 stages
#define STG_PITCH 132

__device__ __forceinline__ void issue_stage(uint32_t sbase, int s, int kc,
                                            int bm, int bn, int tid) {
    uint32_t stage = sbase + s * STAGE_BYTES;
#pragma unroll
    for (int i = 0; i < 4; i++) {                    // A: 128 rows x 8 chunks
        int c = i * 256 + tid;
        int row = c >> 3, ch = c & 7;
        uint32_t dst = stage + row * 128 + ((ch * 16) ^ ((row & 7) << 4));
        cp16(dst, &g_Abf[(size_t)(bm + row) * D_DIM + kc * 64 + ch * 8]);
    }
#pragma unroll
    for (int i = 0; i < 4; i++) {                    // B: 128 rows x 8 chunks (padded, no guard)
        int c = i * 256 + tid;
        int row = c >> 3, ch = c & 7;
        uint32_t dst = stage + 16384 + row * 128 + ((ch * 16) ^ ((row & 7) << 4));
        cp16(dst, &g_Wbf[(size_t)(bn + row) * D_DIM + kc * 64 + ch * 8]);
    }
}

__global__ __launch_bounds__(256, 2) void gemm_mma_kernel(
    const float* __restrict__ bias,  // [V]
    float* __restrict__ C)           // [M, V]
{
    extern __shared__ char smem[];
    uint32_t sbase = smem_u32(smem);

    const int tid  = threadIdx.x;
    const int wid  = tid >> 5;
    const int lane = tid & 31;
    const int bm = blockIdx.y * BM;
    const int bn = blockIdx.x * BN;

    // warp layout: 2 warps along M (64 each), 4 along N (32 each)
    const int m0 = (wid & 1) * 64;
    const int n0 = (wid >> 1) * 32;

    float acc[4][4][4];
#pragma unroll
    for (int mt = 0; mt < 4; mt++)
#pragma unroll
        for (int nt = 0; nt < 4; nt++)
#pragma unroll
            for (int r = 0; r < 4; r++) acc[mt][nt][r] = 0.f;

    const int a_row  = m0 + (lane & 15);
    const int a_kb   = (lane >> 4) * 16;                        // byte sub-offset
    const int b_row  = n0 + (lane & 7) + ((lane >> 4) << 3);
    const int b_kb   = ((lane >> 3) & 1) * 16;

    issue_stage(sbase, 0, 0, bm, bn, tid);
    asm volatile("cp.async.commit_group;");
    issue_stage(sbase, 1, 1, bm, bn, tid);
    asm volatile("cp.async.commit_group;");

#pragma unroll
    for (int kc = 0; kc < 4; kc++) {
        asm volatile("cp.async.wait_group 1;");
        __syncthreads();
        if (kc < 2) {
            issue_stage(sbase, (kc + 2) % 3, kc + 2, bm, bn, tid);
        }
        asm volatile("cp.async.commit_group;");

        uint32_t abase = sbase + (kc % 3) * STAGE_BYTES;
        uint32_t bbase = abase + 16384;
#pragma unroll
        for (int kk = 0; kk < 4; kk++) {
            uint32_t af[4][4], bfr[2][4];
#pragma unroll
            for (int mt = 0; mt < 4; mt++) {
                int r = a_row + mt * 16;
                uint32_t addr = abase + r * 128 + ((kk * 32 + a_kb) ^ ((r & 7) << 4));
                asm volatile("ldmatrix.sync.aligned.m8n8.x4.shared.b16 {%0,%1,%2,%3}, [%4];"
                             : "=r"(af[mt][0]), "=r"(af[mt][1]), "=r"(af[mt][2]), "=r"(af[mt][3])
                             : "r"(addr));
            }
#pragma unroll
            for (int np = 0; np < 2; np++) {
                int r = b_row + np * 16;
                uint32_t addr = bbase + r * 128 + ((kk * 32 + b_kb) ^ ((r & 7) << 4));
                asm volatile("ldmatrix.sync.aligned.m8n8.x4.shared.b16 {%0,%1,%2,%3}, [%4];"
                             : "=r"(bfr[np][0]), "=r"(bfr[np][1]), "=r"(bfr[np][2]), "=r"(bfr[np][3])
                             : "r"(addr));
            }
#pragma unroll
            for (int mt = 0; mt < 4; mt++)
#pragma unroll
                for (int nt = 0; nt < 4; nt++) {
                    asm volatile(
                        "mma.sync.aligned.m16n8k16.row.col.f32.bf16.bf16.f32 "
                        "{%0,%1,%2,%3}, {%4,%5,%6,%7}, {%8,%9}, {%0,%1,%2,%3};"
                        : "+f"(acc[mt][nt][0]), "+f"(acc[mt][nt][1]),
                          "+f"(acc[mt][nt][2]), "+f"(acc[mt][nt][3])
                        : "r"(af[mt][0]), "r"(af[mt][1]), "r"(af[mt][2]), "r"(af[mt][3]),
                          "r"(bfr[nt >> 1][(nt & 1) * 2]), "r"(bfr[nt >> 1][(nt & 1) * 2 + 1]));
                }
        }
    }
    __syncthreads();

    // ---- epilogue: stage in smem, coalesced stores with bias ----
    float* stage = reinterpret_cast<float*>(smem);
    {
        const int crow = lane >> 2;
        const int ccol = (lane & 3) * 2;
#pragma unroll
        for (int mt = 0; mt < 4; mt++)
#pragma unroll
            for (int nt = 0; nt < 4; nt++) {
                int r0 = m0 + mt * 16 + crow;
                int c0 = n0 + nt * 8 + ccol;
                *reinterpret_cast<float2*>(&stage[r0 * STG_PITCH + c0]) =
                    make_float2(acc[mt][nt][0], acc[mt][nt][1]);
                *reinterpret_cast<float2*>(&stage[(r0 + 8) * STG_PITCH + c0]) =
                    make_float2(acc[mt][nt][2], acc[mt][nt][3]);
            }
    }
    __syncthreads();
#pragma unroll 8
    for (int i = 0; i < 64; i++) {
        int idx = i * 256 + tid;
        int col = idx & 127;
        int row = idx >> 7;
        int gc = bn + col;
        if (gc < V_DIM)
            C[(size_t)(bm + row) * V_DIM + gc] = stage[row * STG_PITCH + col] + bias[gc];
    }
}

// ---------------------------------------------------------------------------
// Kernel 2: register-resident log_softmax + CTC emission PROBABILITY gather.
// ---------------------------------------------------------------------------
__global__ __launch_bounds__(256) void logsoftmax_kernel(
    float* __restrict__ logits,      // [M, V] in/out (bias already added)
    const int* __restrict__ y)       // [U, B]
{
    __shared__ float red[8];

    const int r = blockIdx.x;        // r = t*16 + b
    const int b = r & 15;
    const int tid = threadIdx.x;
    const int lane = tid & 31;
    const int wid = tid >> 5;
    float* p = logits + (size_t)r * V_DIM;

    // early raw-logit gather for the CTC emission (reads before any writes)
    float e_raw = 0.f;
    if (tid < S_DIM) {
        int lab = (tid & 1) ? y[((tid - 1) >> 1) * B_DIM + b] : 0;
        e_raw = p[lab];
    }

    float x[16];
    float m = -INFINITY;
#pragma unroll
    for (int i = 0; i < 16; i++) {
        int v = tid + i * 256;
        x[i] = (v < V_DIM) ? p[v] : -INFINITY;
        m = fmaxf(m, x[i]);
    }
#pragma unroll
    for (int s = 16; s > 0; s >>= 1)
        m = fmaxf(m, __shfl_xor_sync(0xffffffffu, m, s));
    if (lane == 0) red[wid] = m;
    __syncthreads();
    if (wid == 0) {
        float t = (lane < 8) ? red[lane] : -INFINITY;
#pragma unroll
        for (int s = 4; s > 0; s >>= 1)
            t = fmaxf(t, __shfl_xor_sync(0xffffffffu, t, s));
        if (lane == 0) red[0] = t;
    }
    __syncthreads();
    float mx = red[0];

    float sum = 0.f;
#pragma unroll
    for (int i = 0; i < 16; i++) sum += __expf(x[i] - mx);   // exp(-inf)=0 for pad
#pragma unroll
    for (int s = 16; s > 0; s >>= 1)
        sum += __shfl_xor_sync(0xffffffffu, sum, s);
    if (lane == 0) red[wid] = sum;
    __syncthreads();
    if (wid == 0) {
        float t = (lane < 8) ? red[lane] : 0.f;
#pragma unroll
        for (int s = 4; s > 0; s >>= 1)
            t += __shfl_xor_sync(0xffffffffu, t, s);
        if (lane == 0) red[0] = t;
    }
    __syncthreads();
    float lse = mx + __logf(red[0]);

    // store PROBABILITY for the linear-domain CTC scan
    if (tid < S_DIM) g_emit[r * SP + tid] = __expf(e_raw - lse);

#pragma unroll
    for (int i = 0; i < 16; i++) {
        int v = tid + i * 256;
        if (v < V_DIM) p[v] = x[i] - lse;
    }
}

// ---------------------------------------------------------------------------
// Kernel 3: linear-domain CTC scan, per-lane block-floating-point scaling,
// renormalized EVERY step (overflow-free by construction: post-renorm a<=1,
// rl<=2^126 applied once => n <= 2^127 < fp32 max). Empty lanes adopt the
// LEFT NEIGHBOR's scale so frontier inflow lands at rl=1.
// ---------------------------------------------------------------------------
__global__ __launch_bounds__(32) void ctc_kernel(
    const int* __restrict__ y,       // [U, B]
    float* __restrict__ out)         // out[0] = loss
{
    __shared__ float afin[SP];
    __shared__ float cfin[32];
    const int b = blockIdx.x;
    const int lane = threadIdx.x;

    // label length (all lanes end with the total)
    int cnt = 0;
    for (int u = lane; u < U_DIM; u += 32) cnt += (y[u * B_DIM + b] != 1);
#pragma unroll
    for (int s = 16; s > 0; s >>= 1) cnt += __shfl_xor_sync(0xffffffffu, cnt, s);

    // static allow masks for my 7 states (s = 7*lane + j)
    float allowf[7];
#pragma unroll
    for (int j = 0; j < 7; j++) {
        int s = 7 * lane + j;
        bool al = false;
        if ((s & 1) && s >= 3 && s < S_DIM) {
            int lab  = y[((s - 1) >> 1) * B_DIM + b];   // ext[s]   (>= 1, so != 0)
            int lab2 = y[((s - 3) >> 1) * B_DIM + b];   // ext[s-2]
            al = (lab != lab2);
        }
        allowf[j] = al ? 1.f : 0.f;
    }

    // per-lane emission base pointer: em(t, j) = gp0[t * (B_DIM*SP) + j]
    const float* gp0 = g_emit + ((size_t)b * SP + 7 * lane);
    const size_t TS = (size_t)B_DIM * SP;   // 3584 floats per t

    float a[7];
    float C  = 0.f;                       // per-lane log2 scale (always finite)
    float rl = 0.f;                       // set by first renorm

    // t = 0 init: alpha = p for s < 2, else 0
#pragma unroll
    for (int j = 0; j < 7; j++) {
        int s = 7 * lane + j;
        a[j] = (s < 2) ? gp0[j] : 0.f;
    }

#define CTC_STEP(EM0, EM1, EM2, EM3, EM4, EM5, EM6)                              \
    {                                                                            \
        float p1 = __shfl_up_sync(0xffffffffu, a[6], 1) * rl;                    \
        float p2 = __shfl_up_sync(0xffffffffu, a[5], 1) * rl;                    \
        float n0 = (a[0] + p1   + p2   * allowf[0]) * (EM0);                     \
        float n1 = (a[1] + a[0] + p1   * allowf[1]) * (EM1);                     \
        float n2 = (a[2] + a[1] + a[0] * allowf[2]) * (EM2);                     \
        float n3 = (a[3] + a[2] + a[1] * allowf[3]) * (EM3);                     \
        float n4 = (a[4] + a[3] + a[2] * allowf[4]) * (EM4);                     \
        float n5 = (a[5] + a[4] + a[3] * allowf[5]) * (EM5);                     \
        float n6 = (a[6] + a[5] + a[4] * allowf[6]) * (EM6);                     \
        a[0] = n0; a[1] = n1; a[2] = n2; a[3] = n3;                              \
        a[4] = n4; a[5] = n5; a[6] = n6;                                         \
    }

    // Per-step renorm: a <= 1 afterwards; C finite; empty lanes track left.
#define CTC_RENORM()                                                             \
    {                                                                            \
        float m = fmaxf(fmaxf(fmaxf(a[0], a[1]), fmaxf(a[2], a[3])),             \
                        fmaxf(fmaxf(a[4], a[5]), a[6]));                         \
        bool nz = (m > 0.f);                                                     \
        if (nz) {                                                                \
            C += __log2f(m);                                                     \
            float inv = 1.0f / m;                                                \
            _Pragma("unroll")                                                    \
            for (int j = 0; j < 7; j++) a[j] *= inv;                             \
        }                                                                        \
        float Cl = __shfl_up_sync(0xffffffffu, C, 1);                            \
        if (!nz && lane > 0) C = Cl;       /* adopt LEFT neighbor's scale */     \
        float Cp = __shfl_up_sync(0xffffffffu, C, 1);                            \
        rl = (lane == 0) ? 0.f : exp2f(fminf(Cp - C, 126.f));                    \
    }

    CTC_RENORM()   // establish scales + rl after init

    // prologue: t = 1, 2, 3
#pragma unroll
    for (int t = 1; t <= 3; t++) {
        const float* em = gp0 + (size_t)t * TS;
        CTC_STEP(em[0], em[1], em[2], em[3], em[4], em[5], em[6])
        CTC_RENORM()
    }

    // main: groups of 4 steps, tb = 4, 8, ..., 796; prefetch next group
    float ec[28], en[28];
#pragma unroll
    for (int g = 0; g < 4; g++)
#pragma unroll
        for (int j = 0; j < 7; j++)
            ec[g * 7 + j] = gp0[(size_t)(4 + g) * TS + j];

    for (int tb = 4; tb < T_DIM; tb += 4) {
        const bool more = (tb + 4 < T_DIM);
#pragma unroll
        for (int g = 0; g < 4; g++)
#pragma unroll
            for (int j = 0; j < 7; j++)
                en[g * 7 + j] = more ? gp0[(size_t)(tb + 4 + g) * TS + j] : 0.f;

        CTC_STEP(ec[0], ec[1], ec[2], ec[3], ec[4], ec[5], ec[6])
        CTC_RENORM()
        CTC_STEP(ec[7], ec[8], ec[9], ec[10], ec[11], ec[12], ec[13])
        CTC_RENORM()
        CTC_STEP(ec[14], ec[15], ec[16], ec[17], ec[18], ec[19], ec[20])
        CTC_RENORM()
        CTC_STEP(ec[21], ec[22], ec[23], ec[24], ec[25], ec[26], ec[27])
        CTC_RENORM()

#pragma unroll
        for (int i = 0; i < 28; i++) ec[i] = en[i];
    }

    // finalize: ll = ln( a[end]*2^C[l(end)] + a[end-1]*2^C[l(end-1)] )
#pragma unroll
    for (int j = 0; j < 7; j++) {
        int s = 7 * lane + j;
        if (s < SP) afin[s] = a[j];
    }
    cfin[lane] = C;
    __syncthreads();
    if (lane == 0) {
        int end = 2 * cnt;
        float v1 = afin[end],     c1 = cfin[end / 7];
        float v2 = afin[end - 1], c2 = cfin[(end - 1) / 7];
        float cm = fmaxf(c1, c2);
        float sum = v1 * exp2f(c1 - cm) + v2 * exp2f(c2 - cm);
        float ll = (cm + __log2f(sum)) * 0.6931471805599453f;
        g_ll[b] = ll;
        __threadfence();
        int ticket = atomicAdd(&g_done, 1);
        if (ticket == B_DIM - 1) {
            __threadfence();
            float s = 0.f;
#pragma unroll
            for (int i = 0; i < B_DIM; i++) s += g_ll[i];
            out[0] = -s;
            g_done = 0;   // reset for next graph replay
        }
    }
}

// ---------------------------------------------------------------------------
// Launch: out = [loss(1), logps(T*B*V)]
// ---------------------------------------------------------------------------
extern "C" void kernel_launch(void* const* d_in, const int* in_sizes, int n_in,
                              void* d_out, int out_size)
{
    const float* ctx  = (const float*)d_in[0];   // [T, B, D]
    const int*   y    = (const int*)  d_in[1];   // [U, B]
    const float* W    = (const float*)d_in[2];   // [D, V]
    const float* bias = (const float*)d_in[3];   // [V]

    float* out   = (float*)d_out;
    float* logps = out + 1;                      // [T, B, V] region

    cudaFuncSetAttribute(gemm_mma_kernel,
                         cudaFuncAttributeMaxDynamicSharedMemorySize, GEMM_SMEM);

    conv_kernel<<<CONV_A_BLKS + CONV_W_BLKS, 256>>>(ctx, W);

    dim3 gemm_grid(VPAD / BN, M_DIM / BM);       // (32, 100)
    gemm_mma_kernel<<<gemm_grid, 256, GEMM_SMEM>>>(bias, logps);
    logsoftmax_kernel<<<M_DIM, 256>>>(logps, y);
    ctc_kernel<<<B_DIM, 32>>>(y, out);
}

// round 15
// speedup vs baseline: 4.2463x; 1.1887x over previous
#include <cuda_runtime.h>
#include <cuda_bf16.h>
#include <math.h>
#include <stdint.h>

// Problem dims (fixed by the dataset)
#define T_DIM 800
#define B_DIM 16
#define D_DIM 256
#define V_DIM 4001
#define VPAD  4096
#define U_DIM 100
#define S_DIM 201              // 2*U+1
#define SP    224              // padded emission stride
#define M_DIM (T_DIM * B_DIM) // 12800

__device__ float g_ll[B_DIM];
__device__ int   g_done = 0;
__device__ float g_emit[M_DIM * SP];                  // emission PROBABILITIES (pads stay 0)
__device__ __nv_bfloat16 g_Abf[M_DIM * D_DIM];        // ctx in bf16
__device__ __nv_bfloat16 g_Wbf[VPAD * D_DIM];         // W^T in bf16 [v][k], zero-padded

__device__ __forceinline__ uint32_t smem_u32(const void* p) {
    uint32_t a;
    asm("{ .reg .u64 t; cvta.to.shared.u64 t, %1; cvt.u32.u64 %0, t; }" : "=r"(a) : "l"(p));
    return a;
}
__device__ __forceinline__ void cp16(uint32_t dst, const void* src) {
    asm volatile("cp.async.cg.shared.global [%0], [%1], 16;" :: "r"(dst), "l"(src));
}

// ---------------------------------------------------------------------------
// Kernel 0: fused input conversion.
// ---------------------------------------------------------------------------
#define CONV_A_BLKS (M_DIM * D_DIM / 4 / 256)   // 3200
#define CONV_W_BLKS ((VPAD / 32) * (D_DIM / 32)) // 1024

__global__ __launch_bounds__(256) void conv_kernel(
    const float* __restrict__ A, const float* __restrict__ W)
{
    if (blockIdx.x < CONV_A_BLKS) {
        int i = blockIdx.x * 256 + threadIdx.x;          // float4 index
        float4 v = reinterpret_cast<const float4*>(A)[i];
        __nv_bfloat162 h0 = __floats2bfloat162_rn(v.x, v.y);
        __nv_bfloat162 h1 = __floats2bfloat162_rn(v.z, v.w);
        uint32_t* out = reinterpret_cast<uint32_t*>(g_Abf);
        out[i * 2]     = *reinterpret_cast<uint32_t*>(&h0);
        out[i * 2 + 1] = *reinterpret_cast<uint32_t*>(&h1);
    } else {
        __shared__ float tile[32][33];
        int bid = blockIdx.x - CONV_A_BLKS;
        int v0 = (bid & 127) * 32;
        int k0 = (bid >> 7) * 32;
        int tx = threadIdx.x & 31;
        int ty = threadIdx.x >> 5;  // 0..7
#pragma unroll
        for (int j = 0; j < 32; j += 8) {
            int k = k0 + ty + j, v = v0 + tx;
            tile[ty + j][tx] = (v < V_DIM) ? W[(size_t)k * V_DIM + v] : 0.f;
        }
        __syncthreads();
#pragma unroll
        for (int j = 0; j < 32; j += 8) {
            int v = v0 + ty + j, k = k0 + tx;
            g_Wbf[(size_t)v * D_DIM + k] = __float2bfloat16(tile[tx][ty + j]);
        }
    }
}

// ---------------------------------------------------------------------------
// Kernel 1: bf16 HMMA GEMM  C[M, V] = A * W + bias.
// CTA 128x128, 3-stage cp.async pipeline over K chunks of 64, warp tile 64x32.
// ---------------------------------------------------------------------------
#define BM 128
#define BN 128
#define STAGE_BYTES 32768           // A 16KB + B 16KB
#define GEMM_SMEM 98304             // 3 stages
#define STG_PITCH 132

__device__ __forceinline__ void issue_stage(uint32_t sbase, int s, int kc,
                                            int bm, int bn, int tid) {
    uint32_t stage = sbase + s * STAGE_BYTES;
#pragma unroll
    for (int i = 0; i < 4; i++) {                    // A: 128 rows x 8 chunks
        int c = i * 256 + tid;
        int row = c >> 3, ch = c & 7;
        uint32_t dst = stage + row * 128 + ((ch * 16) ^ ((row & 7) << 4));
        cp16(dst, &g_Abf[(size_t)(bm + row) * D_DIM + kc * 64 + ch * 8]);
    }
#pragma unroll
    for (int i = 0; i < 4; i++) {                    // B: 128 rows x 8 chunks (padded, no guard)
        int c = i * 256 + tid;
        int row = c >> 3, ch = c & 7;
        uint32_t dst = stage + 16384 + row * 128 + ((ch * 16) ^ ((row & 7) << 4));
        cp16(dst, &g_Wbf[(size_t)(bn + row) * D_DIM + kc * 64 + ch * 8]);
    }
}

__global__ __launch_bounds__(256, 2) void gemm_mma_kernel(
    const float* __restrict__ bias,  // [V]
    float* __restrict__ C)           // [M, V]
{
    extern __shared__ char smem[];
    uint32_t sbase = smem_u32(smem);

    const int tid  = threadIdx.x;
    const int wid  = tid >> 5;
    const int lane = tid & 31;
    const int bm = blockIdx.y * BM;
    const int bn = blockIdx.x * BN;

    // warp layout: 2 warps along M (64 each), 4 along N (32 each)
    const int m0 = (wid & 1) * 64;
    const int n0 = (wid >> 1) * 32;

    float acc[4][4][4];
#pragma unroll
    for (int mt = 0; mt < 4; mt++)
#pragma unroll
        for (int nt = 0; nt < 4; nt++)
#pragma unroll
            for (int r = 0; r < 4; r++) acc[mt][nt][r] = 0.f;

    const int a_row  = m0 + (lane & 15);
    const int a_kb   = (lane >> 4) * 16;                        // byte sub-offset
    const int b_row  = n0 + (lane & 7) + ((lane >> 4) << 3);
    const int b_kb   = ((lane >> 3) & 1) * 16;

    issue_stage(sbase, 0, 0, bm, bn, tid);
    asm volatile("cp.async.commit_group;");
    issue_stage(sbase, 1, 1, bm, bn, tid);
    asm volatile("cp.async.commit_group;");

#pragma unroll
    for (int kc = 0; kc < 4; kc++) {
        asm volatile("cp.async.wait_group 1;");
        __syncthreads();
        if (kc < 2) {
            issue_stage(sbase, (kc + 2) % 3, kc + 2, bm, bn, tid);
        }
        asm volatile("cp.async.commit_group;");

        uint32_t abase = sbase + (kc % 3) * STAGE_BYTES;
        uint32_t bbase = abase + 16384;
#pragma unroll
        for (int kk = 0; kk < 4; kk++) {
            uint32_t af[4][4], bfr[2][4];
#pragma unroll
            for (int mt = 0; mt < 4; mt++) {
                int r = a_row + mt * 16;
                uint32_t addr = abase + r * 128 + ((kk * 32 + a_kb) ^ ((r & 7) << 4));
                asm volatile("ldmatrix.sync.aligned.m8n8.x4.shared.b16 {%0,%1,%2,%3}, [%4];"
                             : "=r"(af[mt][0]), "=r"(af[mt][1]), "=r"(af[mt][2]), "=r"(af[mt][3])
                             : "r"(addr));
            }
#pragma unroll
            for (int np = 0; np < 2; np++) {
                int r = b_row + np * 16;
                uint32_t addr = bbase + r * 128 + ((kk * 32 + b_kb) ^ ((r & 7) << 4));
                asm volatile("ldmatrix.sync.aligned.m8n8.x4.shared.b16 {%0,%1,%2,%3}, [%4];"
                             : "=r"(bfr[np][0]), "=r"(bfr[np][1]), "=r"(bfr[np][2]), "=r"(bfr[np][3])
                             : "r"(addr));
            }
#pragma unroll
            for (int mt = 0; mt < 4; mt++)
#pragma unroll
                for (int nt = 0; nt < 4; nt++) {
                    asm volatile(
                        "mma.sync.aligned.m16n8k16.row.col.f32.bf16.bf16.f32 "
                        "{%0,%1,%2,%3}, {%4,%5,%6,%7}, {%8,%9}, {%0,%1,%2,%3};"
                        : "+f"(acc[mt][nt][0]), "+f"(acc[mt][nt][1]),
                          "+f"(acc[mt][nt][2]), "+f"(acc[mt][nt][3])
                        : "r"(af[mt][0]), "r"(af[mt][1]), "r"(af[mt][2]), "r"(af[mt][3]),
                          "r"(bfr[nt >> 1][(nt & 1) * 2]), "r"(bfr[nt >> 1][(nt & 1) * 2 + 1]));
                }
        }
    }
    __syncthreads();

    // ---- epilogue: stage in smem, coalesced stores with bias ----
    float* stage = reinterpret_cast<float*>(smem);
    {
        const int crow = lane >> 2;
        const int ccol = (lane & 3) * 2;
#pragma unroll
        for (int mt = 0; mt < 4; mt++)
#pragma unroll
            for (int nt = 0; nt < 4; nt++) {
                int r0 = m0 + mt * 16 + crow;
                int c0 = n0 + nt * 8 + ccol;
                *reinterpret_cast<float2*>(&stage[r0 * STG_PITCH + c0]) =
                    make_float2(acc[mt][nt][0], acc[mt][nt][1]);
                *reinterpret_cast<float2*>(&stage[(r0 + 8) * STG_PITCH + c0]) =
                    make_float2(acc[mt][nt][2], acc[mt][nt][3]);
            }
    }
    __syncthreads();
#pragma unroll 8
    for (int i = 0; i < 64; i++) {
        int idx = i * 256 + tid;
        int col = idx & 127;
        int row = idx >> 7;
        int gc = bn + col;
        if (gc < V_DIM)
            C[(size_t)(bm + row) * V_DIM + gc] = stage[row * STG_PITCH + col] + bias[gc];
    }
}

// ---------------------------------------------------------------------------
// Kernel 2: register-resident log_softmax + CTC emission PROBABILITY gather.
// ---------------------------------------------------------------------------
__global__ __launch_bounds__(256) void logsoftmax_kernel(
    float* __restrict__ logits,      // [M, V] in/out (bias already added)
    const int* __restrict__ y)       // [U, B]
{
    __shared__ float red[8];

    const int r = blockIdx.x;        // r = t*16 + b
    const int b = r & 15;
    const int tid = threadIdx.x;
    const int lane = tid & 31;
    const int wid = tid >> 5;
    float* p = logits + (size_t)r * V_DIM;

    // early raw-logit gather for the CTC emission (reads before any writes)
    float e_raw = 0.f;
    if (tid < S_DIM) {
        int lab = (tid & 1) ? y[((tid - 1) >> 1) * B_DIM + b] : 0;
        e_raw = p[lab];
    }

    float x[16];
    float m = -INFINITY;
#pragma unroll
    for (int i = 0; i < 16; i++) {
        int v = tid + i * 256;
        x[i] = (v < V_DIM) ? p[v] : -INFINITY;
        m = fmaxf(m, x[i]);
    }
#pragma unroll
    for (int s = 16; s > 0; s >>= 1)
        m = fmaxf(m, __shfl_xor_sync(0xffffffffu, m, s));
    if (lane == 0) red[wid] = m;
    __syncthreads();
    if (wid == 0) {
        float t = (lane < 8) ? red[lane] : -INFINITY;
#pragma unroll
        for (int s = 4; s > 0; s >>= 1)
            t = fmaxf(t, __shfl_xor_sync(0xffffffffu, t, s));
        if (lane == 0) red[0] = t;
    }
    __syncthreads();
    float mx = red[0];

    float sum = 0.f;
#pragma unroll
    for (int i = 0; i < 16; i++) sum += __expf(x[i] - mx);   // exp(-inf)=0 for pad
#pragma unroll
    for (int s = 16; s > 0; s >>= 1)
        sum += __shfl_xor_sync(0xffffffffu, sum, s);
    if (lane == 0) red[wid] = sum;
    __syncthreads();
    if (wid == 0) {
        float t = (lane < 8) ? red[lane] : 0.f;
#pragma unroll
        for (int s = 4; s > 0; s >>= 1)
            t += __shfl_xor_sync(0xffffffffu, t, s);
        if (lane == 0) red[0] = t;
    }
    __syncthreads();
    float lse = mx + __logf(red[0]);

    // store PROBABILITY for the linear-domain CTC scan
    if (tid < S_DIM) g_emit[r * SP + tid] = __expf(e_raw - lse);

#pragma unroll
    for (int i = 0; i < 16; i++) {
        int v = tid + i * 256;
        if (v < V_DIM) p[v] = x[i] - lse;
    }
}

// ---------------------------------------------------------------------------
// Kernel 3: linear-domain CTC scan, per-lane block-floating-point scaling.
// INTEGER-exponent renorm every step: zero MUFU in the hot loop.
//   true alpha(s) = a[j] * 2^C[lane], C int.
//   scale = 2^(127-e) built from exponent bits (exact);
//   rl = 2^(Cp-C) built from exponent bits, clamp d<=124 (overflow-free:
//   post-renorm a<4, p<=2^126, n<=2^127.6 < fp32 max).
// ---------------------------------------------------------------------------
__global__ __launch_bounds__(32) void ctc_kernel(
    const int* __restrict__ y,       // [U, B]
    float* __restrict__ out)         // out[0] = loss
{
    __shared__ float afin[SP];
    __shared__ int   cfin[32];
    const int b = blockIdx.x;
    const int lane = threadIdx.x;

    // label length (all lanes end with the total)
    int cnt = 0;
    for (int u = lane; u < U_DIM; u += 32) cnt += (y[u * B_DIM + b] != 1);
#pragma unroll
    for (int s = 16; s > 0; s >>= 1) cnt += __shfl_xor_sync(0xffffffffu, cnt, s);

    // static allow masks for my 7 states (s = 7*lane + j)
    float allowf[7];
#pragma unroll
    for (int j = 0; j < 7; j++) {
        int s = 7 * lane + j;
        bool al = false;
        if ((s & 1) && s >= 3 && s < S_DIM) {
            int lab  = y[((s - 1) >> 1) * B_DIM + b];   // ext[s]   (>= 1, so != 0)
            int lab2 = y[((s - 3) >> 1) * B_DIM + b];   // ext[s-2]
            al = (lab != lab2);
        }
        allowf[j] = al ? 1.f : 0.f;
    }

    // per-lane emission base pointer: em(t, j) = gp0[t * (B_DIM*SP) + j]
    const float* gp0 = g_emit + ((size_t)b * SP + 7 * lane);
    const size_t TS = (size_t)B_DIM * SP;   // 3584 floats per t

    float a[7];
    int   C  = 0;                         // per-lane log2 scale (int, always finite)
    float rl = 0.f;                       // set by first renorm

    // t = 0 init: alpha = p for s < 2, else 0
#pragma unroll
    for (int j = 0; j < 7; j++) {
        int s = 7 * lane + j;
        a[j] = (s < 2) ? gp0[j] : 0.f;
    }

// One fused step + integer renorm. All ALU; no MUFU.
#define CTC_STEP(EM0, EM1, EM2, EM3, EM4, EM5, EM6)                              \
    {                                                                            \
        float p1 = __shfl_up_sync(0xffffffffu, a[6], 1) * rl;                    \
        float p2 = __shfl_up_sync(0xffffffffu, a[5], 1) * rl;                    \
        float n0 = (a[0] + p1   + p2   * allowf[0]) * (EM0);                     \
        float n1 = (a[1] + a[0] + p1   * allowf[1]) * (EM1);                     \
        float n2 = (a[2] + a[1] + a[0] * allowf[2]) * (EM2);                     \
        float n3 = (a[3] + a[2] + a[1] * allowf[3]) * (EM3);                     \
        float n4 = (a[4] + a[3] + a[2] * allowf[4]) * (EM4);                     \
        float n5 = (a[5] + a[4] + a[3] * allowf[5]) * (EM5);                     \
        float n6 = (a[6] + a[5] + a[4] * allowf[6]) * (EM6);                     \
        float m = fmaxf(fmaxf(fmaxf(n0, n1), fmaxf(n2, n3)),                     \
                        fmaxf(fmaxf(n4, n5), n6));                               \
        int e = __float_as_int(m) >> 23;          /* biased exponent, >=0 */     \
        e = (e > 253) ? 253 : e;                                                 \
        bool nz = (e > 0);                                                       \
        float scale = nz ? __int_as_float((254 - e) << 23) : 1.0f;               \
        if (nz) C += e - 127;                                                    \
        a[0] = n0 * scale; a[1] = n1 * scale; a[2] = n2 * scale;                 \
        a[3] = n3 * scale; a[4] = n4 * scale; a[5] = n5 * scale;                 \
        a[6] = n6 * scale;                                                       \
        int Cl = __shfl_up_sync(0xffffffffu, C, 1);                              \
        if (!nz && lane > 0) C = Cl;       /* empty lane tracks left */          \
        int Cp = __shfl_up_sync(0xffffffffu, C, 1);                              \
        int d = Cp - C; d = (d > 124) ? 124 : d;                                 \
        rl = (lane == 0 || d < -126) ? 0.f : __int_as_float((127 + d) << 23);    \
    }

// Initial renorm on a[] to establish scales + rl (same math, n == a).
    {
        float m = fmaxf(fmaxf(fmaxf(a[0], a[1]), fmaxf(a[2], a[3])),
                        fmaxf(fmaxf(a[4], a[5]), a[6]));
        int e = __float_as_int(m) >> 23;
        e = (e > 253) ? 253 : e;
        bool nz = (e > 0);
        float scale = nz ? __int_as_float((254 - e) << 23) : 1.0f;
        if (nz) C += e - 127;
#pragma unroll
        for (int j = 0; j < 7; j++) a[j] *= scale;
        int Cl = __shfl_up_sync(0xffffffffu, C, 1);
        if (!nz && lane > 0) C = Cl;
        int Cp = __shfl_up_sync(0xffffffffu, C, 1);
        int d = Cp - C; d = (d > 124) ? 124 : d;
        rl = (lane == 0 || d < -126) ? 0.f : __int_as_float((127 + d) << 23);
    }

    // prologue: t = 1, 2, 3
#pragma unroll
    for (int t = 1; t <= 3; t++) {
        const float* em = gp0 + (size_t)t * TS;
        CTC_STEP(em[0], em[1], em[2], em[3], em[4], em[5], em[6])
    }

    // main: groups of 4 steps, tb = 4, 8, ..., 796; prefetch next group
    float ec[28], en[28];
#pragma unroll
    for (int g = 0; g < 4; g++)
#pragma unroll
        for (int j = 0; j < 7; j++)
            ec[g * 7 + j] = gp0[(size_t)(4 + g) * TS + j];

    for (int tb = 4; tb < T_DIM; tb += 4) {
        const bool more = (tb + 4 < T_DIM);
#pragma unroll
        for (int g = 0; g < 4; g++)
#pragma unroll
            for (int j = 0; j < 7; j++)
                en[g * 7 + j] = more ? gp0[(size_t)(tb + 4 + g) * TS + j] : 0.f;

        CTC_STEP(ec[0], ec[1], ec[2], ec[3], ec[4], ec[5], ec[6])
        CTC_STEP(ec[7], ec[8], ec[9], ec[10], ec[11], ec[12], ec[13])
        CTC_STEP(ec[14], ec[15], ec[16], ec[17], ec[18], ec[19], ec[20])
        CTC_STEP(ec[21], ec[22], ec[23], ec[24], ec[25], ec[26], ec[27])

#pragma unroll
        for (int i = 0; i < 28; i++) ec[i] = en[i];
    }

    // finalize: ll = ln( a[end]*2^C[l(end)] + a[end-1]*2^C[l(end-1)] )
#pragma unroll
    for (int j = 0; j < 7; j++) {
        int s = 7 * lane + j;
        if (s < SP) afin[s] = a[j];
    }
    cfin[lane] = C;
    __syncthreads();
    if (lane == 0) {
        int end = 2 * cnt;
        float v1 = afin[end];     int c1 = cfin[end / 7];
        float v2 = afin[end - 1]; int c2 = cfin[(end - 1) / 7];
        int   cm = (c1 > c2) ? c1 : c2;
        float sum = v1 * exp2f((float)(c1 - cm)) + v2 * exp2f((float)(c2 - cm));
        float ll = ((float)cm + __log2f(sum)) * 0.6931471805599453f;
        g_ll[b] = ll;
        __threadfence();
        int ticket = atomicAdd(&g_done, 1);
        if (ticket == B_DIM - 1) {
            __threadfence();
            float s = 0.f;
#pragma unroll
            for (int i = 0; i < B_DIM; i++) s += g_ll[i];
            out[0] = -s;
            g_done = 0;   // reset for next graph replay
        }
    }
}

// ---------------------------------------------------------------------------
// Launch: out = [loss(1), logps(T*B*V)]
// ---------------------------------------------------------------------------
extern "C" void kernel_launch(void* const* d_in, const int* in_sizes, int n_in,
                              void* d_out, int out_size)
{
    const float* ctx  = (const float*)d_in[0];   // [T, B, D]
    const int*   y    = (const int*)  d_in[1];   // [U, B]
    const float* W    = (const float*)d_in[2];   // [D, V]
    const float* bias = (const float*)d_in[3];   // [V]

    float* out   = (float*)d_out;
    float* logps = out + 1;                      // [T, B, V] region

    cudaFuncSetAttribute(gemm_mma_kernel,
                         cudaFuncAttributeMaxDynamicSharedMemorySize, GEMM_SMEM);

    conv_kernel<<<CONV_A_BLKS + CONV_W_BLKS, 256>>>(ctx, W);

    dim3 gemm_grid(VPAD / BN, M_DIM / BM);       // (32, 100)
    gemm_mma_kernel<<<gemm_grid, 256, GEMM_SMEM>>>(bias, logps);
    logsoftmax_kernel<<<M_DIM, 256>>>(logps, y);
    ctc_kernel<<<B_DIM, 32>>>(y, out);
}

// round 16
// speedup vs baseline: 5.3323x; 1.2557x over previous
#include <cuda_runtime.h>
#include <cuda_bf16.h>
#include <math.h>
#include <stdint.h>

// Problem dims (fixed by the dataset)
#define T_DIM 800
#define B_DIM 16
#define D_DIM 256
#define V_DIM 4001
#define VPAD  4096
#define U_DIM 100
#define S_DIM 201              // 2*U+1
#define SP    224              // padded emission stride
#define M_DIM (T_DIM * B_DIM) // 12800

__device__ float g_ll[B_DIM];
__device__ int   g_done = 0;
__device__ float g_emit[M_DIM * SP];                  // emission PROBABILITIES (pads stay 0)
__device__ __nv_bfloat16 g_Abf[M_DIM * D_DIM];        // ctx in bf16
__device__ __nv_bfloat16 g_Wbf[VPAD * D_DIM];         // W^T in bf16 [v][k], zero-padded

__device__ __forceinline__ uint32_t smem_u32(const void* p) {
    uint32_t a;
    asm("{ .reg .u64 t; cvta.to.shared.u64 t, %1; cvt.u32.u64 %0, t; }" : "=r"(a) : "l"(p));
    return a;
}
__device__ __forceinline__ void cp16(uint32_t dst, const void* src) {
    asm volatile("cp.async.cg.shared.global [%0], [%1], 16;" :: "r"(dst), "l"(src));
}

// ---------------------------------------------------------------------------
// Kernel 0: fused input conversion.
// ---------------------------------------------------------------------------
#define CONV_A_BLKS (M_DIM * D_DIM / 4 / 256)   // 3200
#define CONV_W_BLKS ((VPAD / 32) * (D_DIM / 32)) // 1024

__global__ __launch_bounds__(256) void conv_kernel(
    const float* __restrict__ A, const float* __restrict__ W)
{
    if (blockIdx.x < CONV_A_BLKS) {
        int i = blockIdx.x * 256 + threadIdx.x;          // float4 index
        float4 v = reinterpret_cast<const float4*>(A)[i];
        __nv_bfloat162 h0 = __floats2bfloat162_rn(v.x, v.y);
        __nv_bfloat162 h1 = __floats2bfloat162_rn(v.z, v.w);
        uint32_t* out = reinterpret_cast<uint32_t*>(g_Abf);
        out[i * 2]     = *reinterpret_cast<uint32_t*>(&h0);
        out[i * 2 + 1] = *reinterpret_cast<uint32_t*>(&h1);
    } else {
        __shared__ float tile[32][33];
        int bid = blockIdx.x - CONV_A_BLKS;
        int v0 = (bid & 127) * 32;
        int k0 = (bid >> 7) * 32;
        int tx = threadIdx.x & 31;
        int ty = threadIdx.x >> 5;  // 0..7
#pragma unroll
        for (int j = 0; j < 32; j += 8) {
            int k = k0 + ty + j, v = v0 + tx;
            tile[ty + j][tx] = (v < V_DIM) ? W[(size_t)k * V_DIM + v] : 0.f;
        }
        __syncthreads();
#pragma unroll
        for (int j = 0; j < 32; j += 8) {
            int v = v0 + ty + j, k = k0 + tx;
            g_Wbf[(size_t)v * D_DIM + k] = __float2bfloat16(tile[tx][ty + j]);
        }
    }
}

// ---------------------------------------------------------------------------
// Kernel 1: bf16 HMMA GEMM  C[M, V] = A * W + bias.
// CTA 128x128, 3-stage cp.async pipeline over K chunks of 64, warp tile 64x32.
// ---------------------------------------------------------------------------
#define BM 128
#define BN 128
#define STAGE_BYTES 32768           // A 16KB + B 16KB
#define GEMM_SMEM 98304             // 3 stages
#define STG_PITCH 132

__device__ __forceinline__ void issue_stage(uint32_t sbase, int s, int kc,
                                            int bm, int bn, int tid) {
    uint32_t stage = sbase + s * STAGE_BYTES;
#pragma unroll
    for (int i = 0; i < 4; i++) {                    // A: 128 rows x 8 chunks
        int c = i * 256 + tid;
        int row = c >> 3, ch = c & 7;
        uint32_t dst = stage + row * 128 + ((ch * 16) ^ ((row & 7) << 4));
        cp16(dst, &g_Abf[(size_t)(bm + row) * D_DIM + kc * 64 + ch * 8]);
    }
#pragma unroll
    for (int i = 0; i < 4; i++) {                    // B: 128 rows x 8 chunks (padded, no guard)
        int c = i * 256 + tid;
        int row = c >> 3, ch = c & 7;
        uint32_t dst = stage + 16384 + row * 128 + ((ch * 16) ^ ((row & 7) << 4));
        cp16(dst, &g_Wbf[(size_t)(bn + row) * D_DIM + kc * 64 + ch * 8]);
    }
}

__global__ __launch_bounds__(256, 2) void gemm_mma_kernel(
    const float* __restrict__ bias,  // [V]
    float* __restrict__ C)           // [M, V]
{
    extern __shared__ char smem[];
    uint32_t sbase = smem_u32(smem);

    const int tid  = threadIdx.x;
    const int wid  = tid >> 5;
    const int lane = tid & 31;
    const int bm = blockIdx.y * BM;
    const int bn = blockIdx.x * BN;

    // warp layout: 2 warps along M (64 each), 4 along N (32 each)
    const int m0 = (wid & 1) * 64;
    const int n0 = (wid >> 1) * 32;

    float acc[4][4][4];
#pragma unroll
    for (int mt = 0; mt < 4; mt++)
#pragma unroll
        for (int nt = 0; nt < 4; nt++)
#pragma unroll
            for (int r = 0; r < 4; r++) acc[mt][nt][r] = 0.f;

    const int a_row  = m0 + (lane & 15);
    const int a_kb   = (lane >> 4) * 16;                        // byte sub-offset
    const int b_row  = n0 + (lane & 7) + ((lane >> 4) << 3);
    const int b_kb   = ((lane >> 3) & 1) * 16;

    issue_stage(sbase, 0, 0, bm, bn, tid);
    asm volatile("cp.async.commit_group;");
    issue_stage(sbase, 1, 1, bm, bn, tid);
    asm volatile("cp.async.commit_group;");

#pragma unroll
    for (int kc = 0; kc < 4; kc++) {
        asm volatile("cp.async.wait_group 1;");
        __syncthreads();
        if (kc < 2) {
            issue_stage(sbase, (kc + 2) % 3, kc + 2, bm, bn, tid);
        }
        asm volatile("cp.async.commit_group;");

        uint32_t abase = sbase + (kc % 3) * STAGE_BYTES;
        uint32_t bbase = abase + 16384;
#pragma unroll
        for (int kk = 0; kk < 4; kk++) {
            uint32_t af[4][4], bfr[2][4];
#pragma unroll
            for (int mt = 0; mt < 4; mt++) {
                int r = a_row + mt * 16;
                uint32_t addr = abase + r * 128 + ((kk * 32 + a_kb) ^ ((r & 7) << 4));
                asm volatile("ldmatrix.sync.aligned.m8n8.x4.shared.b16 {%0,%1,%2,%3}, [%4];"
                             : "=r"(af[mt][0]), "=r"(af[mt][1]), "=r"(af[mt][2]), "=r"(af[mt][3])
                             : "r"(addr));
            }
#pragma unroll
            for (int np = 0; np < 2; np++) {
                int r = b_row + np * 16;
                uint32_t addr = bbase + r * 128 + ((kk * 32 + b_kb) ^ ((r & 7) << 4));
                asm volatile("ldmatrix.sync.aligned.m8n8.x4.shared.b16 {%0,%1,%2,%3}, [%4];"
                             : "=r"(bfr[np][0]), "=r"(bfr[np][1]), "=r"(bfr[np][2]), "=r"(bfr[np][3])
                             : "r"(addr));
            }
#pragma unroll
            for (int mt = 0; mt < 4; mt++)
#pragma unroll
                for (int nt = 0; nt < 4; nt++) {
                    asm volatile(
                        "mma.sync.aligned.m16n8k16.row.col.f32.bf16.bf16.f32 "
                        "{%0,%1,%2,%3}, {%4,%5,%6,%7}, {%8,%9}, {%0,%1,%2,%3};"
                        : "+f"(acc[mt][nt][0]), "+f"(acc[mt][nt][1]),
                          "+f"(acc[mt][nt][2]), "+f"(acc[mt][nt][3])
                        : "r"(af[mt][0]), "r"(af[mt][1]), "r"(af[mt][2]), "r"(af[mt][3]),
                          "r"(bfr[nt >> 1][(nt & 1) * 2]), "r"(bfr[nt >> 1][(nt & 1) * 2 + 1]));
                }
        }
    }
    __syncthreads();

    // ---- epilogue: stage in smem, coalesced stores with bias ----
    float* stage = reinterpret_cast<float*>(smem);
    {
        const int crow = lane >> 2;
        const int ccol = (lane & 3) * 2;
#pragma unroll
        for (int mt = 0; mt < 4; mt++)
#pragma unroll
            for (int nt = 0; nt < 4; nt++) {
                int r0 = m0 + mt * 16 + crow;
                int c0 = n0 + nt * 8 + ccol;
                *reinterpret_cast<float2*>(&stage[r0 * STG_PITCH + c0]) =
                    make_float2(acc[mt][nt][0], acc[mt][nt][1]);
                *reinterpret_cast<float2*>(&stage[(r0 + 8) * STG_PITCH + c0]) =
                    make_float2(acc[mt][nt][2], acc[mt][nt][3]);
            }
    }
    __syncthreads();
#pragma unroll 8
    for (int i = 0; i < 64; i++) {
        int idx = i * 256 + tid;
        int col = idx & 127;
        int row = idx >> 7;
        int gc = bn + col;
        if (gc < V_DIM)
            C[(size_t)(bm + row) * V_DIM + gc] = stage[row * STG_PITCH + col] + bias[gc];
    }
}

// ---------------------------------------------------------------------------
// Kernel 2: register-resident log_softmax + CTC emission PROBABILITY gather.
// ---------------------------------------------------------------------------
__global__ __launch_bounds__(256) void logsoftmax_kernel(
    float* __restrict__ logits,      // [M, V] in/out (bias already added)
    const int* __restrict__ y)       // [U, B]
{
    __shared__ float red[8];

    const int r = blockIdx.x;        // r = t*16 + b
    const int b = r & 15;
    const int tid = threadIdx.x;
    const int lane = tid & 31;
    const int wid = tid >> 5;
    float* p = logits + (size_t)r * V_DIM;

    // early raw-logit gather for the CTC emission (reads before any writes)
    float e_raw = 0.f;
    if (tid < S_DIM) {
        int lab = (tid & 1) ? y[((tid - 1) >> 1) * B_DIM + b] : 0;
        e_raw = p[lab];
    }

    float x[16];
    float m = -INFINITY;
#pragma unroll
    for (int i = 0; i < 16; i++) {
        int v = tid + i * 256;
        x[i] = (v < V_DIM) ? p[v] : -INFINITY;
        m = fmaxf(m, x[i]);
    }
#pragma unroll
    for (int s = 16; s > 0; s >>= 1)
        m = fmaxf(m, __shfl_xor_sync(0xffffffffu, m, s));
    if (lane == 0) red[wid] = m;
    __syncthreads();
    if (wid == 0) {
        float t = (lane < 8) ? red[lane] : -INFINITY;
#pragma unroll
        for (int s = 4; s > 0; s >>= 1)
            t = fmaxf(t, __shfl_xor_sync(0xffffffffu, t, s));
        if (lane == 0) red[0] = t;
    }
    __syncthreads();
    float mx = red[0];

    float sum = 0.f;
#pragma unroll
    for (int i = 0; i < 16; i++) sum += __expf(x[i] - mx);   // exp(-inf)=0 for pad
#pragma unroll
    for (int s = 16; s > 0; s >>= 1)
        sum += __shfl_xor_sync(0xffffffffu, sum, s);
    if (lane == 0) red[wid] = sum;
    __syncthreads();
    if (wid == 0) {
        float t = (lane < 8) ? red[lane] : 0.f;
#pragma unroll
        for (int s = 4; s > 0; s >>= 1)
            t += __shfl_xor_sync(0xffffffffu, t, s);
        if (lane == 0) red[0] = t;
    }
    __syncthreads();
    float lse = mx + __logf(red[0]);

    // store PROBABILITY for the linear-domain CTC scan
    if (tid < S_DIM) g_emit[r * SP + tid] = __expf(e_raw - lse);

#pragma unroll
    for (int i = 0; i < 16; i++) {
        int v = tid + i * 256;
        if (v < V_DIM) p[v] = x[i] - lse;
    }
}

// ---------------------------------------------------------------------------
// Kernel 3: linear-domain CTC scan, per-lane block-floating-point scaling.
// Integer-exponent renorm every step, SINGLE C-shfl per step (merged adopt +
// ratio: if the left lane is empty its outgoing alpha is 0, so a stale Cl is
// multiplied by zero and harmless). A/B double-buffered emission prefetch
// (distance 4-8 steps) removes the 28-reg copy per group.
// ---------------------------------------------------------------------------
__global__ __launch_bounds__(32) void ctc_kernel(
    const int* __restrict__ y,       // [U, B]
    float* __restrict__ out)         // out[0] = loss
{
    __shared__ float afin[SP];
    __shared__ int   cfin[32];
    const int b = blockIdx.x;
    const int lane = threadIdx.x;

    // label length (all lanes end with the total)
    int cnt = 0;
    for (int u = lane; u < U_DIM; u += 32) cnt += (y[u * B_DIM + b] != 1);
#pragma unroll
    for (int s = 16; s > 0; s >>= 1) cnt += __shfl_xor_sync(0xffffffffu, cnt, s);

    // static allow masks for my 7 states (s = 7*lane + j)
    float allowf[7];
#pragma unroll
    for (int j = 0; j < 7; j++) {
        int s = 7 * lane + j;
        bool al = false;
        if ((s & 1) && s >= 3 && s < S_DIM) {
            int lab  = y[((s - 1) >> 1) * B_DIM + b];   // ext[s]   (>= 1, so != 0)
            int lab2 = y[((s - 3) >> 1) * B_DIM + b];   // ext[s-2]
            al = (lab != lab2);
        }
        allowf[j] = al ? 1.f : 0.f;
    }

    // per-lane emission base pointer: em(t, j) = gp0[t * (B_DIM*SP) + j]
    const float* gp0 = g_emit + ((size_t)b * SP + 7 * lane);
    const size_t TS = (size_t)B_DIM * SP;   // 3584 floats per t

    float a[7];
    int   C  = 0;                         // per-lane log2 scale (int, always finite)
    float rl = 0.f;                       // set by first renorm

    // t = 0 init: alpha = p for s < 2, else 0
#pragma unroll
    for (int j = 0; j < 7; j++) {
        int s = 7 * lane + j;
        a[j] = (s < 2) ? gp0[j] : 0.f;
    }

// One fused step + integer renorm + merged single C-shfl. All ALU; no MUFU.
#define CTC_STEP(EM0, EM1, EM2, EM3, EM4, EM5, EM6)                              \
    {                                                                            \
        float p1 = __shfl_up_sync(0xffffffffu, a[6], 1) * rl;                    \
        float p2 = __shfl_up_sync(0xffffffffu, a[5], 1) * rl;                    \
        float n0 = (a[0] + p1   + p2   * allowf[0]) * (EM0);                     \
        float n1 = (a[1] + a[0] + p1   * allowf[1]) * (EM1);                     \
        float n2 = (a[2] + a[1] + a[0] * allowf[2]) * (EM2);                     \
        float n3 = (a[3] + a[2] + a[1] * allowf[3]) * (EM3);                     \
        float n4 = (a[4] + a[3] + a[2] * allowf[4]) * (EM4);                     \
        float n5 = (a[5] + a[4] + a[3] * allowf[5]) * (EM5);                     \
        float n6 = (a[6] + a[5] + a[4] * allowf[6]) * (EM6);                     \
        float m = fmaxf(fmaxf(fmaxf(n0, n1), fmaxf(n2, n3)),                     \
                        fmaxf(fmaxf(n4, n5), n6));                               \
        int e = __float_as_int(m) >> 23;          /* biased exponent, >=0 */     \
        e = (e > 253) ? 253 : e;                                                 \
        bool nz = (e > 0);                                                       \
        float scale = nz ? __int_as_float((254 - e) << 23) : 1.0f;               \
        if (nz) C += e - 127;                                                    \
        a[0] = n0 * scale; a[1] = n1 * scale; a[2] = n2 * scale;                 \
        a[3] = n3 * scale; a[4] = n4 * scale; a[5] = n5 * scale;                 \
        a[6] = n6 * scale;                                                       \
        int Cl = __shfl_up_sync(0xffffffffu, C, 1);                              \
        if (!nz && lane > 0) C = Cl;       /* empty lane tracks left */          \
        int d = Cl - C; d = (d > 124) ? 124 : d;                                 \
        rl = (lane == 0 || d < -126) ? 0.f : __int_as_float((127 + d) << 23);    \
    }

// Initial renorm on a[] to establish scales + rl (same math, n == a).
    {
        float m = fmaxf(fmaxf(fmaxf(a[0], a[1]), fmaxf(a[2], a[3])),
                        fmaxf(fmaxf(a[4], a[5]), a[6]));
        int e = __float_as_int(m) >> 23;
        e = (e > 253) ? 253 : e;
        bool nz = (e > 0);
        float scale = nz ? __int_as_float((254 - e) << 23) : 1.0f;
        if (nz) C += e - 127;
#pragma unroll
        for (int j = 0; j < 7; j++) a[j] *= scale;
        int Cl = __shfl_up_sync(0xffffffffu, C, 1);
        if (!nz && lane > 0) C = Cl;
        int d = Cl - C; d = (d > 124) ? 124 : d;
        rl = (lane == 0 || d < -126) ? 0.f : __int_as_float((127 + d) << 23);
    }

    // prologue: t = 1, 2, 3
#pragma unroll
    for (int t = 1; t <= 3; t++) {
        const float* em = gp0 + (size_t)t * TS;
        CTC_STEP(em[0], em[1], em[2], em[3], em[4], em[5], em[6])
    }

    // main: 8-step body, A/B double-buffered prefetch (no register copies).
    // Invariant at loop head: eA = steps[tb..tb+3], eB = steps[tb+4..tb+7].
    float eA[28], eB[28];
#pragma unroll
    for (int g = 0; g < 4; g++)
#pragma unroll
        for (int j = 0; j < 7; j++) {
            eA[g * 7 + j] = gp0[(size_t)(4 + g) * TS + j];
            eB[g * 7 + j] = gp0[(size_t)(8 + g) * TS + j];
        }

    for (int tb = 4; tb <= 788; tb += 8) {
        CTC_STEP(eA[0], eA[1], eA[2], eA[3], eA[4], eA[5], eA[6])
        CTC_STEP(eA[7], eA[8], eA[9], eA[10], eA[11], eA[12], eA[13])
        CTC_STEP(eA[14], eA[15], eA[16], eA[17], eA[18], eA[19], eA[20])
        CTC_STEP(eA[21], eA[22], eA[23], eA[24], eA[25], eA[26], eA[27])
        // reload A with steps tb+8 .. tb+11 (tb+11 <= 799 for all tb <= 788)
#pragma unroll
        for (int g = 0; g < 4; g++)
#pragma unroll
            for (int j = 0; j < 7; j++)
                eA[g * 7 + j] = gp0[(size_t)(tb + 8 + g) * TS + j];

        CTC_STEP(eB[0], eB[1], eB[2], eB[3], eB[4], eB[5], eB[6])
        CTC_STEP(eB[7], eB[8], eB[9], eB[10], eB[11], eB[12], eB[13])
        CTC_STEP(eB[14], eB[15], eB[16], eB[17], eB[18], eB[19], eB[20])
        CTC_STEP(eB[21], eB[22], eB[23], eB[24], eB[25], eB[26], eB[27])
        // reload B with steps tb+12 .. tb+15 (guard the tail)
        const bool morel = (tb + 15 < T_DIM);
#pragma unroll
        for (int g = 0; g < 4; g++)
#pragma unroll
            for (int j = 0; j < 7; j++)
                eB[g * 7 + j] = morel ? gp0[(size_t)(tb + 12 + g) * TS + j] : 0.f;
    }

    // epilogue: steps 796..799 live in eA (loaded during tb = 788)
    CTC_STEP(eA[0], eA[1], eA[2], eA[3], eA[4], eA[5], eA[6])
    CTC_STEP(eA[7], eA[8], eA[9], eA[10], eA[11], eA[12], eA[13])
    CTC_STEP(eA[14], eA[15], eA[16], eA[17], eA[18], eA[19], eA[20])
    CTC_STEP(eA[21], eA[22], eA[23], eA[24], eA[25], eA[26], eA[27])

    // finalize: ll = ln( a[end]*2^C[l(end)] + a[end-1]*2^C[l(end-1)] )
#pragma unroll
    for (int j = 0; j < 7; j++) {
        int s = 7 * lane + j;
        if (s < SP) afin[s] = a[j];
    }
    cfin[lane] = C;
    __syncthreads();
    if (lane == 0) {
        int end = 2 * cnt;
        float v1 = afin[end];     int c1 = cfin[end / 7];
        float v2 = afin[end - 1]; int c2 = cfin[(end - 1) / 7];
        int   cm = (c1 > c2) ? c1 : c2;
        float sum = v1 * exp2f((float)(c1 - cm)) + v2 * exp2f((float)(c2 - cm));
        float ll = ((float)cm + __log2f(sum)) * 0.6931471805599453f;
        g_ll[b] = ll;
        __threadfence();
        int ticket = atomicAdd(&g_done, 1);
        if (ticket == B_DIM - 1) {
            __threadfence();
            float s = 0.f;
#pragma unroll
            for (int i = 0; i < B_DIM; i++) s += g_ll[i];
            out[0] = -s;
            g_done = 0;   // reset for next graph replay
        }
    }
}

// ---------------------------------------------------------------------------
// Launch: out = [loss(1), logps(T*B*V)]
// ---------------------------------------------------------------------------
extern "C" void kernel_launch(void* const* d_in, const int* in_sizes, int n_in,
                              void* d_out, int out_size)
{
    const float* ctx  = (const float*)d_in[0];   // [T, B, D]
    const int*   y    = (const int*)  d_in[1];   // [U, B]
    const float* W    = (const float*)d_in[2];   // [D, V]
    const float* bias = (const float*)d_in[3];   // [V]

    float* out   = (float*)d_out;
    float* logps = out + 1;                      // [T, B, V] region

    cudaFuncSetAttribute(gemm_mma_kernel,
                         cudaFuncAttributeMaxDynamicSharedMemorySize, GEMM_SMEM);

    conv_kernel<<<CONV_A_BLKS + CONV_W_BLKS, 256>>>(ctx, W);

    dim3 gemm_grid(VPAD / BN, M_DIM / BM);       // (32, 100)
    gemm_mma_kernel<<<gemm_grid, 256, GEMM_SMEM>>>(bias, logps);
    logsoftmax_kernel<<<M_DIM, 256>>>(logps, y);
    ctc_kernel<<<B_DIM, 32>>>(y, out);
}